// round 1
// baseline (speedup 1.0000x reference)
#include <cuda_runtime.h>
#include <math.h>

#define BDIM 128
#define LDIM 128
#define NNEI 6
#define FAA 39
#define FBB 10
#define FC 49
#define DD 200
#define D2 400
#define D3 600
#define RR 3
#define TTI 2
#define MBOND 256
#define NEGV -9e8f
#define NATOM (BDIM*LDIM)    /* 16384 */
#define NROWN (NATOM*NNEI)   /* 98304 */

// ---------------- device scratch (static, no allocation) ----------------
__device__ float g_atomfeat[NATOM*DD];
__device__ float g_h[NATOM*DD];
__device__ float g_cur[NATOM*DD];
__device__ float g_ctx[NATOM*DD];
__device__ float g_concat[NROWN*FC];
__device__ float g_nei0[NROWN*DD];
__device__ float g_trans0[NROWN*DD];
__device__ float g_transA[NATOM*DD];
__device__ float g_gi[NATOM*D3];
__device__ float g_gh[NATOM*D3];
__device__ float g_s2[NATOM];
__device__ float g_transm[NATOM*DD];
__device__ float g_mol[BDIM*DD];
__device__ float g_actmol[BDIM*DD];
__device__ float g_mctx[BDIM*DD];
__device__ float g_mgi[BDIM*D3];
__device__ float g_mgh[BDIM*D3];

// ---------------- helpers ----------------
__device__ __forceinline__ float warpsum(float v) {
    #pragma unroll
    for (int o = 16; o > 0; o >>= 1) v += __shfl_down_sync(0xffffffffu, v, o);
    return v;
}

__device__ __forceinline__ float lrelu(float x) { return x > 0.f ? x : 0.01f * x; }
__device__ __forceinline__ float eluf(float x)  { return x > 0.f ? x : expm1f(x); }
__device__ __forceinline__ float sigm(float x)  { return 1.f / (1.f + expf(-x)); }

// ---------------- generic tiled SGEMM: C = act(A @ B (+bias)) ----------------
// A [M,K] row-major. TRANSB=0: B [K,N] row-major.  TRANSB=1: B [N,K] row-major (y = x @ B^T).
template<int TRANSB, int ACT>
__global__ void sgemm_kernel(const float* __restrict__ A, const float* __restrict__ Bm,
                             const float* __restrict__ bias, float* __restrict__ C,
                             int M, int N, int K)
{
    __shared__ float As[16][65];
    __shared__ float Bs[16][65];
    const int tid = threadIdx.x;
    const int tx = tid & 15;       // n micro
    const int ty = tid >> 4;       // m micro
    const int m0 = blockIdx.y * 64 + ty * 4;
    const int n0 = blockIdx.x * 64 + tx * 4;
    float acc[4][4] = {};

    for (int k0 = 0; k0 < K; k0 += 16) {
        {   // A tile: 64 rows x 16 k
            int ka = tid & 15;
            int ma = tid >> 4;
            int k = k0 + ka;
            #pragma unroll
            for (int i = 0; i < 4; i++) {
                int m = blockIdx.y * 64 + ma + i * 16;
                As[ka][ma + i * 16] = (m < M && k < K) ? A[(size_t)m * K + k] : 0.f;
            }
        }
        if (TRANSB) {
            int kb = tid & 15;
            int nb = tid >> 4;
            int k = k0 + kb;
            #pragma unroll
            for (int i = 0; i < 4; i++) {
                int n = blockIdx.x * 64 + nb + i * 16;
                Bs[kb][nb + i * 16] = (n < N && k < K) ? Bm[(size_t)n * K + k] : 0.f;
            }
        } else {
            int nb = tid & 63;
            int kb = tid >> 6;
            int n = blockIdx.x * 64 + nb;
            #pragma unroll
            for (int i = 0; i < 4; i++) {
                int k = k0 + kb + i * 4;
                Bs[kb + i * 4][nb] = (n < N && k < K) ? Bm[(size_t)k * N + n] : 0.f;
            }
        }
        __syncthreads();
        #pragma unroll
        for (int kk = 0; kk < 16; kk++) {
            float ra[4], rb[4];
            #pragma unroll
            for (int i = 0; i < 4; i++) ra[i] = As[kk][ty * 4 + i];
            #pragma unroll
            for (int j = 0; j < 4; j++) rb[j] = Bs[kk][tx * 4 + j];
            #pragma unroll
            for (int i = 0; i < 4; i++)
                #pragma unroll
                for (int j = 0; j < 4; j++)
                    acc[i][j] += ra[i] * rb[j];
        }
        __syncthreads();
    }

    #pragma unroll
    for (int i = 0; i < 4; i++) {
        int m = m0 + i;
        if (m >= M) continue;
        #pragma unroll
        for (int j = 0; j < 4; j++) {
            int n = n0 + j;
            if (n >= N) continue;
            float v = acc[i][j] + (bias ? bias[n] : 0.f);
            if (ACT == 1) v = lrelu(v);
            C[(size_t)m * N + n] = v;
        }
    }
}

// ---------------- elementwise copy ----------------
__global__ void copy_kernel(float* __restrict__ dst, const float* __restrict__ src, int n)
{
    int i = blockIdx.x * blockDim.x + threadIdx.x;
    if (i < n) dst[i] = src[i];
}

// ---------------- build concat(atom_nei, bond_nei) [NROWN, FC] ----------------
__global__ void build_concat(const float* __restrict__ atom_list,
                             const float* __restrict__ bond_list,
                             const int* __restrict__ adeg,
                             const int* __restrict__ bdeg,
                             float* __restrict__ out)
{
    int i = blockIdx.x * blockDim.x + threadIdx.x;
    if (i >= NROWN * FC) return;
    int row = i / FC;
    int f = i - row * FC;
    int b = row / (LDIM * NNEI);
    float v;
    if (f < FAA) {
        int a = adeg[row];
        v = atom_list[((size_t)b * LDIM + a) * FAA + f];
    } else {
        int bd = bdeg[row];
        v = bond_list[((size_t)b * MBOND + bd) * FBB + (f - FAA)];
    }
    out[i] = v;
}

// ---------------- attention context per atom ----------------
// firstRound: nei/trans read from [NROWN, D] buffers; else nei = gather(cur), trans = gather(transA)
__global__ void ctx_kernel(const float* __restrict__ cur,
                           const float* __restrict__ neiBuf,
                           const float* __restrict__ transBuf,
                           const int* __restrict__ adeg,
                           const float* __restrict__ Wal,  // 2D floats
                           const float* __restrict__ bal,  // 1 float
                           float* __restrict__ ctx,
                           int firstRound)
{
    const int atom = blockIdx.x;
    const int b = atom / LDIM;
    const int tid = threadIdx.x;
    const int lane = tid & 31;

    __shared__ float curS[DD];
    __shared__ float red[NNEI + 1];

    if (tid <= NNEI) red[tid] = 0.f;
    for (int d = tid; d < DD; d += 256) curS[d] = cur[(size_t)atom * DD + d];
    __syncthreads();

    int idx[NNEI];
    const float* neirow[NNEI];
    #pragma unroll
    for (int n = 0; n < NNEI; n++) {
        idx[n] = adeg[atom * NNEI + n];
        neirow[n] = firstRound ? (neiBuf + ((size_t)atom * NNEI + n) * DD)
                               : (cur + ((size_t)(b * LDIM + idx[n])) * DD);
    }

    float p[NNEI + 1];
    #pragma unroll
    for (int n = 0; n <= NNEI; n++) p[n] = 0.f;
    for (int d = tid; d < DD; d += 256) {
        float a1 = Wal[d];
        float a2 = Wal[DD + d];
        p[NNEI] += a1 * curS[d];
        #pragma unroll
        for (int n = 0; n < NNEI; n++) p[n] += a2 * neirow[n][d];
    }
    #pragma unroll
    for (int n = 0; n <= NNEI; n++) {
        float s = warpsum(p[n]);
        if (lane == 0) atomicAdd(&red[n], s);
    }
    __syncthreads();

    // softmax over neighbors (all threads redundantly)
    float dtop = red[NNEI];
    float bb = bal[0];
    float sc[NNEI];
    float msk[NNEI];
    float mx = -1e30f;
    #pragma unroll
    for (int n = 0; n < NNEI; n++) {
        float a = lrelu(dtop + red[n] + bb);
        bool pad = (idx[n] == LDIM - 1);
        msk[n] = pad ? 0.f : 1.f;
        a += pad ? NEGV : 0.f;
        sc[n] = a;
        mx = fmaxf(mx, a);
    }
    float sum = 0.f;
    float w[NNEI];
    #pragma unroll
    for (int n = 0; n < NNEI; n++) { w[n] = expf(sc[n] - mx); sum += w[n]; }
    float inv = 1.f / sum;
    #pragma unroll
    for (int n = 0; n < NNEI; n++) w[n] = w[n] * inv * msk[n];

    const float* trow[NNEI];
    #pragma unroll
    for (int n = 0; n < NNEI; n++)
        trow[n] = firstRound ? (transBuf + ((size_t)atom * NNEI + n) * DD)
                             : (transBuf + ((size_t)(b * LDIM + idx[n])) * DD);

    for (int d = tid; d < DD; d += 256) {
        float s = 0.f;
        #pragma unroll
        for (int n = 0; n < NNEI; n++) s += w[n] * trow[n][d];
        ctx[(size_t)atom * DD + d] = eluf(s);
    }
}

// ---------------- GRU combine ----------------
__global__ void gru_combine(const float* __restrict__ gi, const float* __restrict__ gh,
                            const float* __restrict__ h,
                            float* __restrict__ hOut, float* __restrict__ actOut, int Mrows)
{
    int i = blockIdx.x * blockDim.x + threadIdx.x;
    if (i >= Mrows * DD) return;
    int m = i / DD;
    int d = i - m * DD;
    const float* gim = gi + (size_t)m * D3;
    const float* ghm = gh + (size_t)m * D3;
    float r = sigm(gim[d] + ghm[d]);
    float z = sigm(gim[DD + d] + ghm[DD + d]);
    float n = tanhf(gim[2 * DD + d] + r * ghm[2 * DD + d]);
    float hv = h[i];
    float hn = (1.f - z) * n + z * hv;
    hOut[i] = hn;
    actOut[i] = hn > 0.f ? hn : 0.f;
}

// ---------------- mol feature = masked sum over atoms ----------------
__global__ void molfeat_kernel(const float* __restrict__ cur, const float* __restrict__ amask,
                               float* __restrict__ mol, float* __restrict__ actmol)
{
    int b = blockIdx.x;
    for (int d = threadIdx.x; d < DD; d += blockDim.x) {
        float s = 0.f;
        for (int l = 0; l < LDIM; l++)
            s += cur[((size_t)b * LDIM + l) * DD + d] * amask[b * LDIM + l];
        mol[b * DD + d] = s;
        actmol[b * DD + d] = s > 0.f ? s : 0.f;
    }
}

// ---------------- per-atom mol-align dot: s2 = cur . Wma[D:2D] ----------------
__global__ void s2_kernel(const float* __restrict__ cur, const float* __restrict__ Wma,
                          float* __restrict__ s2)
{
    int row = blockIdx.x * (blockDim.x >> 5) + (threadIdx.x >> 5);
    int lane = threadIdx.x & 31;
    if (row >= NATOM) return;
    float p = 0.f;
    for (int d = lane; d < DD; d += 32)
        p += cur[(size_t)row * DD + d] * Wma[DD + d];
    p = warpsum(p);
    if (lane == 0) s2[row] = p;
}

// ---------------- mol attention context ----------------
__global__ void molctx_kernel(const float* __restrict__ actmol,
                              const float* __restrict__ transm,
                              const float* __restrict__ s2,
                              const float* __restrict__ amask,
                              const float* __restrict__ Wma,
                              const float* __restrict__ bma,
                              float* __restrict__ mctx)
{
    int b = blockIdx.x;
    int tid = threadIdx.x;
    int lane = tid & 31;
    __shared__ float redv;
    __shared__ float sc[LDIM];
    __shared__ float wS[LDIM];
    if (tid == 0) redv = 0.f;
    __syncthreads();

    float p = 0.f;
    for (int d = tid; d < DD; d += 256) p += actmol[b * DD + d] * Wma[d];
    p = warpsum(p);
    if (lane == 0) atomicAdd(&redv, p);
    __syncthreads();

    if (tid < LDIM) {
        float a = lrelu(redv + s2[b * LDIM + tid] + bma[0]);
        if (amask[b * LDIM + tid] == 0.f) a += NEGV;
        sc[tid] = a;
    }
    __syncthreads();

    float mx = -1e30f;
    for (int l = 0; l < LDIM; l++) mx = fmaxf(mx, sc[l]);
    float sum = 0.f;
    for (int l = 0; l < LDIM; l++) sum += expf(sc[l] - mx);
    float inv = 1.f / sum;
    if (tid < LDIM) wS[tid] = expf(sc[tid] - mx) * inv * amask[b * LDIM + tid];
    __syncthreads();

    for (int d = tid; d < DD; d += 256) {
        float s = 0.f;
        for (int l = 0; l < LDIM; l++)
            s += wS[l] * transm[((size_t)b * LDIM + l) * DD + d];
        mctx[b * DD + d] = eluf(s);
    }
}

// ---------------- final projection ----------------
__global__ void final_kernel(const float* __restrict__ mol,
                             const float* __restrict__ Wm, const float* __restrict__ bm,
                             const float* __restrict__ Wo, const float* __restrict__ bo,
                             float* __restrict__ out)
{
    int b = blockIdx.x;
    int tid = threadIdx.x;
    int lane = tid & 31;
    __shared__ float featS[D2];
    __shared__ float ws[8];
    for (int j = tid; j < D2; j += 256)
        featS[j] = (j < DD) ? mol[b * DD + j] : (mol[b * DD + j - DD] + (float)(RR - 2));
    __syncthreads();
    float p = 0.f;
    for (int d = tid; d < DD; d += 256) {
        float s = bm[d];
        for (int j = 0; j < D2; j++) s += featS[j] * Wm[j * DD + d];
        p += s * Wo[d];
    }
    p = warpsum(p);
    if (lane == 0) ws[tid >> 5] = p;
    __syncthreads();
    if (tid == 0) {
        float t = 0.f;
        for (int i = 0; i < 8; i++) t += ws[i];
        out[b] = t + bo[0];
    }
}

// ---------------- host-side GEMM dispatch ----------------
static void sgemm(const float* A, const float* Bm, const float* bias, float* C,
                  int M, int N, int K, int transB, int act)
{
    dim3 g((N + 63) / 64, (M + 63) / 64), blk(256);
    if (transB) {
        if (act) sgemm_kernel<1, 1><<<g, blk>>>(A, Bm, bias, C, M, N, K);
        else     sgemm_kernel<1, 0><<<g, blk>>>(A, Bm, bias, C, M, N, K);
    } else {
        if (act) sgemm_kernel<0, 1><<<g, blk>>>(A, Bm, bias, C, M, N, K);
        else     sgemm_kernel<0, 0><<<g, blk>>>(A, Bm, bias, C, M, N, K);
    }
}

extern "C" void kernel_launch(void* const* d_in, const int* in_sizes, int n_in,
                              void* d_out, int out_size)
{
    const float* atom_list   = (const float*)d_in[0];
    const float* bond_list   = (const float*)d_in[1];
    const int*   adeg        = (const int*)d_in[2];
    const int*   bdeg        = (const int*)d_in[3];
    const float* amask       = (const float*)d_in[4];
    const float* W_atom      = (const float*)d_in[5];
    const float* b_atom      = (const float*)d_in[6];
    const float* W_nei       = (const float*)d_in[7];
    const float* b_nei       = (const float*)d_in[8];
    const float* W_align     = (const float*)d_in[9];
    const float* b_align     = (const float*)d_in[10];
    const float* W_attend    = (const float*)d_in[11];
    const float* b_attend    = (const float*)d_in[12];
    const float* Wih         = (const float*)d_in[13];
    const float* Whh         = (const float*)d_in[14];
    const float* bih         = (const float*)d_in[15];
    const float* bhh         = (const float*)d_in[16];
    const float* W_mol_align = (const float*)d_in[17];
    const float* b_mol_align = (const float*)d_in[18];
    const float* W_mol_att   = (const float*)d_in[19];
    const float* b_mol_att   = (const float*)d_in[20];
    const float* mWih        = (const float*)d_in[21];
    const float* mWhh        = (const float*)d_in[22];
    const float* mbih        = (const float*)d_in[23];
    const float* mbhh        = (const float*)d_in[24];
    const float* W_metric    = (const float*)d_in[25];
    const float* b_metric    = (const float*)d_in[26];
    const float* W_out       = (const float*)d_in[27];
    const float* b_out       = (const float*)d_in[28];

    float *atomfeat, *h, *cur, *ctx, *concat, *nei0, *trans0, *transA, *gi, *gh;
    float *s2, *transm, *mol, *actmol, *mctx, *mgi, *mgh;
    cudaGetSymbolAddress((void**)&atomfeat, g_atomfeat);
    cudaGetSymbolAddress((void**)&h, g_h);
    cudaGetSymbolAddress((void**)&cur, g_cur);
    cudaGetSymbolAddress((void**)&ctx, g_ctx);
    cudaGetSymbolAddress((void**)&concat, g_concat);
    cudaGetSymbolAddress((void**)&nei0, g_nei0);
    cudaGetSymbolAddress((void**)&trans0, g_trans0);
    cudaGetSymbolAddress((void**)&transA, g_transA);
    cudaGetSymbolAddress((void**)&gi, g_gi);
    cudaGetSymbolAddress((void**)&gh, g_gh);
    cudaGetSymbolAddress((void**)&s2, g_s2);
    cudaGetSymbolAddress((void**)&transm, g_transm);
    cudaGetSymbolAddress((void**)&mol, g_mol);
    cudaGetSymbolAddress((void**)&actmol, g_actmol);
    cudaGetSymbolAddress((void**)&mctx, g_mctx);
    cudaGetSymbolAddress((void**)&mgi, g_mgi);
    cudaGetSymbolAddress((void**)&mgh, g_mgh);

    // 1) atom_feature = lrelu(atom_list @ W_atom + b_atom)
    sgemm(atom_list, W_atom, b_atom, atomfeat, NATOM, DD, FAA, 0, 1);
    copy_kernel<<<(NATOM * DD + 255) / 256, 256>>>(h, atomfeat, NATOM * DD);
    copy_kernel<<<(NATOM * DD + 255) / 256, 256>>>(cur, atomfeat, NATOM * DD);

    // 2) nei0 = lrelu(concat(atom_nei, bond_nei) @ W_nei + b_nei)
    build_concat<<<(NROWN * FC + 255) / 256, 256>>>(atom_list, bond_list, adeg, bdeg, concat);
    sgemm(concat, W_nei, b_nei, nei0, NROWN, DD, FC, 0, 1);

    // 3) atom GRU rounds
    for (int r = 0; r < RR; r++) {
        if (r == 0) {
            sgemm(nei0, W_attend, b_attend, trans0, NROWN, DD, DD, 0, 0);
            ctx_kernel<<<NATOM, 256>>>(cur, nei0, trans0, adeg, W_align, b_align, ctx, 1);
        } else {
            sgemm(cur, W_attend + (size_t)r * DD * DD, b_attend + r * DD, transA, NATOM, DD, DD, 0, 0);
            ctx_kernel<<<NATOM, 256>>>(cur, nullptr, transA, adeg,
                                       W_align + (size_t)r * D2, b_align + r, ctx, 0);
        }
        sgemm(ctx, Wih + (size_t)r * D3 * DD, bih + r * D3, gi, NATOM, D3, DD, 1, 0);
        sgemm(h,   Whh + (size_t)r * D3 * DD, bhh + r * D3, gh, NATOM, D3, DD, 1, 0);
        gru_combine<<<(NATOM * DD + 255) / 256, 256>>>(gi, gh, h, h, cur, NATOM);
    }

    // 4) mol phase
    molfeat_kernel<<<BDIM, 256>>>(cur, amask, mol, actmol);
    s2_kernel<<<(NATOM + 7) / 8, 256>>>(cur, W_mol_align, s2);
    sgemm(cur, W_mol_att, b_mol_att, transm, NATOM, DD, DD, 0, 0);
    for (int t = 0; t < TTI; t++) {
        molctx_kernel<<<BDIM, 256>>>(actmol, transm, s2, amask, W_mol_align, b_mol_align, mctx);
        sgemm(mctx, mWih, mbih, mgi, BDIM, D3, DD, 1, 0);
        sgemm(mol,  mWhh, mbhh, mgh, BDIM, D3, DD, 1, 0);
        gru_combine<<<(BDIM * DD + 255) / 256, 256>>>(mgi, mgh, mol, mol, actmol, BDIM);
    }

    // 5) final projection
    final_kernel<<<BDIM, 256>>>(mol, W_metric, b_metric, W_out, b_out, (float*)d_out);
}

// round 4
// speedup vs baseline: 1.1941x; 1.1941x over previous
#include <cuda_runtime.h>
#include <math.h>

typedef unsigned long long u64;

#define BDIM 128
#define LDIM 128
#define NNEI 6
#define FAA 39
#define FBB 10
#define FC 49
#define DD 200
#define D2 400
#define D3 600
#define RR 3
#define TTI 2
#define MBOND 256
#define NEGV -9e8f
#define NATOM (BDIM*LDIM)    /* 16384 */
#define NROWN (NATOM*NNEI)   /* 98304 */
#define KPAD 64

// ---------------- device scratch (static, no allocation) ----------------
__device__ float g_atomfeat[NATOM*DD];
__device__ float g_atompad[NATOM*KPAD];
__device__ float g_h[NATOM*DD];
__device__ float g_cur[NATOM*DD];
__device__ float g_ctx[NATOM*DD];
__device__ float g_concat[NROWN*KPAD];
__device__ float g_nei0[NROWN*DD];
__device__ float g_trans0[NROWN*DD];
__device__ float g_transA[NATOM*DD];
__device__ float g_gi[NATOM*D3];
__device__ float g_gh[NATOM*D3];
__device__ float g_s2[NATOM];
__device__ float g_transm[NATOM*DD];
__device__ float g_mol[BDIM*DD];
__device__ float g_actmol[BDIM*DD];
__device__ float g_mctx[BDIM*DD];
__device__ float g_mgi[BDIM*D3];
__device__ float g_mgh[BDIM*D3];

// ---------------- helpers ----------------
__device__ __forceinline__ float warpsum(float v) {
    #pragma unroll
    for (int o = 16; o > 0; o >>= 1) v += __shfl_down_sync(0xffffffffu, v, o);
    return v;
}
__device__ __forceinline__ float lrelu(float x) { return x > 0.f ? x : 0.01f * x; }
__device__ __forceinline__ float eluf(float x)  { return x > 0.f ? x : expm1f(x); }
__device__ __forceinline__ float sigm(float x)  { return 1.f / (1.f + expf(-x)); }

__device__ __forceinline__ u64 splat2(float x) {
    u64 r; asm("mov.b64 %0, {%1, %1};" : "=l"(r) : "f"(x)); return r;
}
__device__ __forceinline__ void fma2(u64& d, u64 a, u64 b) {
    asm("fma.rn.f32x2 %0, %1, %2, %0;" : "+l"(d) : "l"(a), "l"(b));
}
__device__ __forceinline__ void unpack2(u64 v, float& lo, float& hi) {
    asm("mov.b64 {%0, %1}, %2;" : "=f"(lo), "=f"(hi) : "l"(v));
}

// =====================================================================
// Packed-fp32 SGEMM: C[M,N] = act(A[M,K](lda) @ B (+bias))
// TRANSB=0: B[K,N] row-major.  TRANSB=1: B[N,K] row-major.
// BM=BN=128, BK=8, 256 threads, 8x8 microtile, f32x2 FMA, double-buffered.
// Requires: M % 128 == 0; lda % 4 == 0; A row window [k0, k0+7] readable;
//           K % 8 == 0 OR (TRANSB==0 with K-guard on B rows); N % 4 == 0 for f4 B loads.
// =====================================================================
template<int TRANSB, int ACT>
__global__ void __launch_bounds__(256, 2) gemm2_kernel(
    const float* __restrict__ A, int lda,
    const float* __restrict__ Bm,
    const float* __restrict__ bias,
    float* __restrict__ C,
    int M, int N, int K)
{
    __shared__ float As[2][8 * 132];
    __shared__ float Bs[2][8 * 132];

    const int tid = threadIdx.x;
    const int tx = tid & 15;         // n micro (8 cols)
    const int ty = tid >> 4;         // m micro (8 rows)
    const int bn0 = blockIdx.x * 128;
    const int bm0 = blockIdx.y * 128;
    const int m0 = ty * 8;
    const int n0 = tx * 8;

    // A loader: 128 rows x 8 k, float4 along k: 1 float4/thread
    const int ar  = tid >> 1;
    const int akc = (tid & 1) * 4;
    // B loader indices
    const int b_nr  = tid >> 1;          // TRANSB=1: n-row in tile
    const int b_kc  = (tid & 1) * 4;     // TRANSB=1: k offset
    const int b_kr  = tid >> 5;          // TRANSB=0: k-row in tile
    const int b_nc  = (tid & 31) * 4;    // TRANSB=0: n offset

    const int ntiles = (K + 7) >> 3;
    float4 aS, bS;

    u64 acc[8][4];
    #pragma unroll
    for (int i = 0; i < 8; i++)
        #pragma unroll
        for (int j = 0; j < 4; j++) acc[i][j] = 0ull;

    // ---- tile 0 load + store ----
    {
        const int k0 = 0;
        aS = *reinterpret_cast<const float4*>(A + (size_t)(bm0 + ar) * lda + k0 + akc);
        if (TRANSB) {
            int n = bn0 + b_nr;
            bS = (n < N) ? *reinterpret_cast<const float4*>(Bm + (size_t)n * K + k0 + b_kc)
                         : make_float4(0.f, 0.f, 0.f, 0.f);
        } else {
            int k = k0 + b_kr, n = bn0 + b_nc;
            bS = (k < K && n < N) ? *reinterpret_cast<const float4*>(Bm + (size_t)k * N + n)
                                  : make_float4(0.f, 0.f, 0.f, 0.f);
        }
        As[0][(akc + 0) * 132 + ar] = aS.x;
        As[0][(akc + 1) * 132 + ar] = aS.y;
        As[0][(akc + 2) * 132 + ar] = aS.z;
        As[0][(akc + 3) * 132 + ar] = aS.w;
        if (TRANSB) {
            Bs[0][(b_kc + 0) * 132 + b_nr] = bS.x;
            Bs[0][(b_kc + 1) * 132 + b_nr] = bS.y;
            Bs[0][(b_kc + 2) * 132 + b_nr] = bS.z;
            Bs[0][(b_kc + 3) * 132 + b_nr] = bS.w;
        } else {
            *reinterpret_cast<float4*>(&Bs[0][b_kr * 132 + b_nc]) = bS;
        }
    }
    __syncthreads();

    for (int t = 0; t < ntiles; t++) {
        const int cur = t & 1;
        if (t + 1 < ntiles) {
            const int k0 = (t + 1) << 3;
            aS = *reinterpret_cast<const float4*>(A + (size_t)(bm0 + ar) * lda + k0 + akc);
            if (TRANSB) {
                int n = bn0 + b_nr;
                bS = (n < N) ? *reinterpret_cast<const float4*>(Bm + (size_t)n * K + k0 + b_kc)
                             : make_float4(0.f, 0.f, 0.f, 0.f);
            } else {
                int k = k0 + b_kr, n = bn0 + b_nc;
                bS = (k < K && n < N) ? *reinterpret_cast<const float4*>(Bm + (size_t)k * N + n)
                                      : make_float4(0.f, 0.f, 0.f, 0.f);
            }
        }

        #pragma unroll
        for (int kk = 0; kk < 8; kk++) {
            const float* arow = &As[cur][kk * 132 + m0];
            float4 a03 = *reinterpret_cast<const float4*>(arow);
            float4 a47 = *reinterpret_cast<const float4*>(arow + 4);
            const u64* brow = reinterpret_cast<const u64*>(&Bs[cur][kk * 132 + n0]);
            u64 b2[4];
            #pragma unroll
            for (int j = 0; j < 4; j++) b2[j] = brow[j];
            u64 a2[8];
            a2[0] = splat2(a03.x); a2[1] = splat2(a03.y);
            a2[2] = splat2(a03.z); a2[3] = splat2(a03.w);
            a2[4] = splat2(a47.x); a2[5] = splat2(a47.y);
            a2[6] = splat2(a47.z); a2[7] = splat2(a47.w);
            #pragma unroll
            for (int i = 0; i < 8; i++)
                #pragma unroll
                for (int j = 0; j < 4; j++)
                    fma2(acc[i][j], a2[i], b2[j]);
        }

        if (t + 1 < ntiles) {
            const int nxt = cur ^ 1;
            As[nxt][(akc + 0) * 132 + ar] = aS.x;
            As[nxt][(akc + 1) * 132 + ar] = aS.y;
            As[nxt][(akc + 2) * 132 + ar] = aS.z;
            As[nxt][(akc + 3) * 132 + ar] = aS.w;
            if (TRANSB) {
                Bs[nxt][(b_kc + 0) * 132 + b_nr] = bS.x;
                Bs[nxt][(b_kc + 1) * 132 + b_nr] = bS.y;
                Bs[nxt][(b_kc + 2) * 132 + b_nr] = bS.z;
                Bs[nxt][(b_kc + 3) * 132 + b_nr] = bS.w;
            } else {
                *reinterpret_cast<float4*>(&Bs[nxt][b_kr * 132 + b_nc]) = bS;
            }
        }
        __syncthreads();
    }

    // ---- epilogue ----
    float bvals[8];
    #pragma unroll
    for (int j = 0; j < 8; j++) {
        int n = bn0 + n0 + j;
        bvals[j] = (bias && n < N) ? bias[n] : 0.f;
    }
    #pragma unroll
    for (int i = 0; i < 8; i++) {
        int m = bm0 + m0 + i;
        if (m >= M) continue;
        float* crow = C + (size_t)m * N;
        #pragma unroll
        for (int j = 0; j < 4; j++) {
            float lo, hi; unpack2(acc[i][j], lo, hi);
            int n = bn0 + n0 + 2 * j;
            if (n < N) {
                float v = lo + bvals[2 * j];
                if (ACT == 1) v = lrelu(v);
                crow[n] = v;
            }
            if (n + 1 < N) {
                float v = hi + bvals[2 * j + 1];
                if (ACT == 1) v = lrelu(v);
                crow[n + 1] = v;
            }
        }
    }
}

// ---------------- elementwise copy ----------------
__global__ void copy_kernel(float* __restrict__ dst, const float* __restrict__ src, int n)
{
    int i = blockIdx.x * blockDim.x + threadIdx.x;
    if (i < n) dst[i] = src[i];
}

// ---------------- pad atom_list [NATOM,39] -> [NATOM,64] ----------------
__global__ void pad_atom_kernel(const float* __restrict__ atom_list, float* __restrict__ out)
{
    int i = blockIdx.x * blockDim.x + threadIdx.x;
    if (i >= NATOM * KPAD) return;
    int row = i >> 6;
    int f = i & 63;
    out[i] = (f < FAA) ? atom_list[row * FAA + f] : 0.f;
}

// ---------------- build concat(atom_nei, bond_nei) [NROWN, 64] padded ----------------
__global__ void build_concat(const float* __restrict__ atom_list,
                             const float* __restrict__ bond_list,
                             const int* __restrict__ adeg,
                             const int* __restrict__ bdeg,
                             float* __restrict__ out)
{
    int i = blockIdx.x * blockDim.x + threadIdx.x;
    if (i >= NROWN * KPAD) return;
    int row = i >> 6;
    int f = i & 63;
    int b = row / (LDIM * NNEI);
    float v = 0.f;
    if (f < FAA) {
        int a = adeg[row];
        v = atom_list[((size_t)b * LDIM + a) * FAA + f];
    } else if (f < FC) {
        int bd = bdeg[row];
        v = bond_list[((size_t)b * MBOND + bd) * FBB + (f - FAA)];
    }
    out[i] = v;
}

// ---------------- attention context per atom ----------------
__global__ void ctx_kernel(const float* __restrict__ cur,
                           const float* __restrict__ neiBuf,
                           const float* __restrict__ transBuf,
                           const int* __restrict__ adeg,
                           const float* __restrict__ Wal,
                           const float* __restrict__ bal,
                           float* __restrict__ ctx,
                           int firstRound)
{
    const int atom = blockIdx.x;
    const int b = atom / LDIM;
    const int tid = threadIdx.x;
    const int lane = tid & 31;

    __shared__ float curS[DD];
    __shared__ float red[NNEI + 1];

    if (tid <= NNEI) red[tid] = 0.f;
    for (int d = tid; d < DD; d += 256) curS[d] = cur[(size_t)atom * DD + d];
    __syncthreads();

    int idx[NNEI];
    const float* neirow[NNEI];
    #pragma unroll
    for (int n = 0; n < NNEI; n++) {
        idx[n] = adeg[atom * NNEI + n];
        neirow[n] = firstRound ? (neiBuf + ((size_t)atom * NNEI + n) * DD)
                               : (cur + ((size_t)(b * LDIM + idx[n])) * DD);
    }

    float p[NNEI + 1];
    #pragma unroll
    for (int n = 0; n <= NNEI; n++) p[n] = 0.f;
    for (int d = tid; d < DD; d += 256) {
        float a1 = Wal[d];
        float a2 = Wal[DD + d];
        p[NNEI] += a1 * curS[d];
        #pragma unroll
        for (int n = 0; n < NNEI; n++) p[n] += a2 * neirow[n][d];
    }
    #pragma unroll
    for (int n = 0; n <= NNEI; n++) {
        float s = warpsum(p[n]);
        if (lane == 0) atomicAdd(&red[n], s);
    }
    __syncthreads();

    float dtop = red[NNEI];
    float bb = bal[0];
    float sc[NNEI];
    float msk[NNEI];
    float mx = -1e30f;
    #pragma unroll
    for (int n = 0; n < NNEI; n++) {
        float a = lrelu(dtop + red[n] + bb);
        bool pad = (idx[n] == LDIM - 1);
        msk[n] = pad ? 0.f : 1.f;
        a += pad ? NEGV : 0.f;
        sc[n] = a;
        mx = fmaxf(mx, a);
    }
    float sum = 0.f;
    float w[NNEI];
    #pragma unroll
    for (int n = 0; n < NNEI; n++) { w[n] = expf(sc[n] - mx); sum += w[n]; }
    float inv = 1.f / sum;
    #pragma unroll
    for (int n = 0; n < NNEI; n++) w[n] = w[n] * inv * msk[n];

    const float* trow[NNEI];
    #pragma unroll
    for (int n = 0; n < NNEI; n++)
        trow[n] = firstRound ? (transBuf + ((size_t)atom * NNEI + n) * DD)
                             : (transBuf + ((size_t)(b * LDIM + idx[n])) * DD);

    for (int d = tid; d < DD; d += 256) {
        float s = 0.f;
        #pragma unroll
        for (int n = 0; n < NNEI; n++) s += w[n] * trow[n][d];
        ctx[(size_t)atom * DD + d] = eluf(s);
    }
}

// ---------------- GRU combine ----------------
__global__ void gru_combine(const float* __restrict__ gi, const float* __restrict__ gh,
                            const float* __restrict__ h,
                            float* __restrict__ hOut, float* __restrict__ actOut, int Mrows)
{
    int i = blockIdx.x * blockDim.x + threadIdx.x;
    if (i >= Mrows * DD) return;
    int m = i / DD;
    int d = i - m * DD;
    const float* gim = gi + (size_t)m * D3;
    const float* ghm = gh + (size_t)m * D3;
    float r = sigm(gim[d] + ghm[d]);
    float z = sigm(gim[DD + d] + ghm[DD + d]);
    float n = tanhf(gim[2 * DD + d] + r * ghm[2 * DD + d]);
    float hv = h[i];
    float hn = (1.f - z) * n + z * hv;
    hOut[i] = hn;
    actOut[i] = hn > 0.f ? hn : 0.f;
}

// ---------------- mol feature = masked sum over atoms ----------------
__global__ void molfeat_kernel(const float* __restrict__ cur, const float* __restrict__ amask,
                               float* __restrict__ mol, float* __restrict__ actmol)
{
    int b = blockIdx.x;
    for (int d = threadIdx.x; d < DD; d += blockDim.x) {
        float s = 0.f;
        for (int l = 0; l < LDIM; l++)
            s += cur[((size_t)b * LDIM + l) * DD + d] * amask[b * LDIM + l];
        mol[b * DD + d] = s;
        actmol[b * DD + d] = s > 0.f ? s : 0.f;
    }
}

// ---------------- per-atom mol-align dot ----------------
__global__ void s2_kernel(const float* __restrict__ cur, const float* __restrict__ Wma,
                          float* __restrict__ s2)
{
    int row = blockIdx.x * (blockDim.x >> 5) + (threadIdx.x >> 5);
    int lane = threadIdx.x & 31;
    if (row >= NATOM) return;
    float p = 0.f;
    for (int d = lane; d < DD; d += 32)
        p += cur[(size_t)row * DD + d] * Wma[DD + d];
    p = warpsum(p);
    if (lane == 0) s2[row] = p;
}

// ---------------- mol attention context ----------------
__global__ void molctx_kernel(const float* __restrict__ actmol,
                              const float* __restrict__ transm,
                              const float* __restrict__ s2,
                              const float* __restrict__ amask,
                              const float* __restrict__ Wma,
                              const float* __restrict__ bma,
                              float* __restrict__ mctx)
{
    int b = blockIdx.x;
    int tid = threadIdx.x;
    int lane = tid & 31;
    __shared__ float redv;
    __shared__ float sc[LDIM];
    __shared__ float wS[LDIM];
    if (tid == 0) redv = 0.f;
    __syncthreads();

    float p = 0.f;
    for (int d = tid; d < DD; d += 256) p += actmol[b * DD + d] * Wma[d];
    p = warpsum(p);
    if (lane == 0) atomicAdd(&redv, p);
    __syncthreads();

    if (tid < LDIM) {
        float a = lrelu(redv + s2[b * LDIM + tid] + bma[0]);
        if (amask[b * LDIM + tid] == 0.f) a += NEGV;
        sc[tid] = a;
    }
    __syncthreads();

    float mx = -1e30f;
    for (int l = 0; l < LDIM; l++) mx = fmaxf(mx, sc[l]);
    float sum = 0.f;
    for (int l = 0; l < LDIM; l++) sum += expf(sc[l] - mx);
    float inv = 1.f / sum;
    if (tid < LDIM) wS[tid] = expf(sc[tid] - mx) * inv * amask[b * LDIM + tid];
    __syncthreads();

    for (int d = tid; d < DD; d += 256) {
        float s = 0.f;
        for (int l = 0; l < LDIM; l++)
            s += wS[l] * transm[((size_t)b * LDIM + l) * DD + d];
        mctx[b * DD + d] = eluf(s);
    }
}

// ---------------- final projection ----------------
__global__ void final_kernel(const float* __restrict__ mol,
                             const float* __restrict__ Wm, const float* __restrict__ bm,
                             const float* __restrict__ Wo, const float* __restrict__ bo,
                             float* __restrict__ out)
{
    int b = blockIdx.x;
    int tid = threadIdx.x;
    int lane = tid & 31;
    __shared__ float featS[D2];
    __shared__ float ws[8];
    for (int j = tid; j < D2; j += 256)
        featS[j] = (j < DD) ? mol[b * DD + j] : (mol[b * DD + j - DD] + (float)(RR - 2));
    __syncthreads();
    float p = 0.f;
    for (int d = tid; d < DD; d += 256) {
        float s = bm[d];
        for (int j = 0; j < D2; j++) s += featS[j] * Wm[j * DD + d];
        p += s * Wo[d];
    }
    p = warpsum(p);
    if (lane == 0) ws[tid >> 5] = p;
    __syncthreads();
    if (tid == 0) {
        float t = 0.f;
        for (int i = 0; i < 8; i++) t += ws[i];
        out[b] = t + bo[0];
    }
}

// ---------------- host-side GEMM dispatch ----------------
static void gemm(const float* A, int lda, const float* Bm, const float* bias, float* C,
                 int M, int N, int K, int transB, int act)
{
    dim3 g((N + 127) / 128, (M + 127) / 128), blk(256);
    if (transB) {
        if (act) gemm2_kernel<1, 1><<<g, blk>>>(A, lda, Bm, bias, C, M, N, K);
        else     gemm2_kernel<1, 0><<<g, blk>>>(A, lda, Bm, bias, C, M, N, K);
    } else {
        if (act) gemm2_kernel<0, 1><<<g, blk>>>(A, lda, Bm, bias, C, M, N, K);
        else     gemm2_kernel<0, 0><<<g, blk>>>(A, lda, Bm, bias, C, M, N, K);
    }
}

extern "C" void kernel_launch(void* const* d_in, const int* in_sizes, int n_in,
                              void* d_out, int out_size)
{
    const float* atom_list   = (const float*)d_in[0];
    const float* bond_list   = (const float*)d_in[1];
    const int*   adeg        = (const int*)d_in[2];
    const int*   bdeg        = (const int*)d_in[3];
    const float* amask       = (const float*)d_in[4];
    const float* W_atom      = (const float*)d_in[5];
    const float* b_atom      = (const float*)d_in[6];
    const float* W_nei       = (const float*)d_in[7];
    const float* b_nei       = (const float*)d_in[8];
    const float* W_align     = (const float*)d_in[9];
    const float* b_align     = (const float*)d_in[10];
    const float* W_attend    = (const float*)d_in[11];
    const float* b_attend    = (const float*)d_in[12];
    const float* Wih         = (const float*)d_in[13];
    const float* Whh         = (const float*)d_in[14];
    const float* bih         = (const float*)d_in[15];
    const float* bhh         = (const float*)d_in[16];
    const float* W_mol_align = (const float*)d_in[17];
    const float* b_mol_align = (const float*)d_in[18];
    const float* W_mol_att   = (const float*)d_in[19];
    const float* b_mol_att   = (const float*)d_in[20];
    const float* mWih        = (const float*)d_in[21];
    const float* mWhh        = (const float*)d_in[22];
    const float* mbih        = (const float*)d_in[23];
    const float* mbhh        = (const float*)d_in[24];
    const float* W_metric    = (const float*)d_in[25];
    const float* b_metric    = (const float*)d_in[26];
    const float* W_out       = (const float*)d_in[27];
    const float* b_out       = (const float*)d_in[28];

    float *atomfeat, *atompad, *h, *cur, *ctx, *concat, *nei0, *trans0, *transA, *gi, *gh;
    float *s2, *transm, *mol, *actmol, *mctx, *mgi, *mgh;
    cudaGetSymbolAddress((void**)&atomfeat, g_atomfeat);
    cudaGetSymbolAddress((void**)&atompad, g_atompad);
    cudaGetSymbolAddress((void**)&h, g_h);
    cudaGetSymbolAddress((void**)&cur, g_cur);
    cudaGetSymbolAddress((void**)&ctx, g_ctx);
    cudaGetSymbolAddress((void**)&concat, g_concat);
    cudaGetSymbolAddress((void**)&nei0, g_nei0);
    cudaGetSymbolAddress((void**)&trans0, g_trans0);
    cudaGetSymbolAddress((void**)&transA, g_transA);
    cudaGetSymbolAddress((void**)&gi, g_gi);
    cudaGetSymbolAddress((void**)&gh, g_gh);
    cudaGetSymbolAddress((void**)&s2, g_s2);
    cudaGetSymbolAddress((void**)&transm, g_transm);
    cudaGetSymbolAddress((void**)&mol, g_mol);
    cudaGetSymbolAddress((void**)&actmol, g_actmol);
    cudaGetSymbolAddress((void**)&mctx, g_mctx);
    cudaGetSymbolAddress((void**)&mgi, g_mgi);
    cudaGetSymbolAddress((void**)&mgh, g_mgh);

    // 1) atom_feature = lrelu(atom_list @ W_atom + b_atom)
    pad_atom_kernel<<<(NATOM * KPAD + 255) / 256, 256>>>(atom_list, atompad);
    gemm(atompad, KPAD, W_atom, b_atom, atomfeat, NATOM, DD, FAA, 0, 1);
    copy_kernel<<<(NATOM * DD + 255) / 256, 256>>>(h, atomfeat, NATOM * DD);
    copy_kernel<<<(NATOM * DD + 255) / 256, 256>>>(cur, atomfeat, NATOM * DD);

    // 2) nei0 = lrelu(concat(atom_nei, bond_nei) @ W_nei + b_nei)
    build_concat<<<(NROWN * KPAD + 255) / 256, 256>>>(atom_list, bond_list, adeg, bdeg, concat);
    gemm(concat, KPAD, W_nei, b_nei, nei0, NROWN, DD, FC, 0, 1);

    // 3) atom GRU rounds
    for (int r = 0; r < RR; r++) {
        if (r == 0) {
            gemm(nei0, DD, W_attend, b_attend, trans0, NROWN, DD, DD, 0, 0);
            ctx_kernel<<<NATOM, 256>>>(cur, nei0, trans0, adeg, W_align, b_align, ctx, 1);
        } else {
            gemm(cur, DD, W_attend + (size_t)r * DD * DD, b_attend + r * DD, transA, NATOM, DD, DD, 0, 0);
            ctx_kernel<<<NATOM, 256>>>(cur, nullptr, transA, adeg,
                                       W_align + (size_t)r * D2, b_align + r, ctx, 0);
        }
        gemm(ctx, DD, Wih + (size_t)r * D3 * DD, bih + r * D3, gi, NATOM, D3, DD, 1, 0);
        gemm(h,   DD, Whh + (size_t)r * D3 * DD, bhh + r * D3, gh, NATOM, D3, DD, 1, 0);
        gru_combine<<<(NATOM * DD + 255) / 256, 256>>>(gi, gh, h, h, cur, NATOM);
    }

    // 4) mol phase
    molfeat_kernel<<<BDIM, 256>>>(cur, amask, mol, actmol);
    s2_kernel<<<(NATOM + 7) / 8, 256>>>(cur, W_mol_align, s2);
    gemm(cur, DD, W_mol_att, b_mol_att, transm, NATOM, DD, DD, 0, 0);
    for (int t = 0; t < TTI; t++) {
        molctx_kernel<<<BDIM, 256>>>(actmol, transm, s2, amask, W_mol_align, b_mol_align, mctx);
        gemm(mctx, DD, mWih, mbih, mgi, BDIM, D3, DD, 1, 0);
        gemm(mol,  DD, mWhh, mbhh, mgh, BDIM, D3, DD, 1, 0);
        gru_combine<<<(BDIM * DD + 255) / 256, 256>>>(mgi, mgh, mol, mol, actmol, BDIM);
    }

    // 5) final projection
    final_kernel<<<BDIM, 256>>>(mol, W_metric, b_metric, W_out, b_out, (float*)d_out);
}

// round 5
// speedup vs baseline: 1.2847x; 1.0759x over previous
#include <cuda_runtime.h>
#include <math.h>

typedef unsigned long long u64;

#define BDIM 128
#define LDIM 128
#define NNEI 6
#define FAA 39
#define FBB 10
#define FC 49
#define DD 200
#define D2 400
#define D3 600
#define RR 3
#define TTI 2
#define MBOND 256
#define NEGV -9e8f
#define NATOM (BDIM*LDIM)    /* 16384 */
#define NROWN (NATOM*NNEI)   /* 98304 */
#define KPAD 64

// ---------------- device scratch (static, no allocation) ----------------
__device__ float g_atomfeat[NATOM*DD];   // also serves as h (updated in place)
__device__ float g_atompad[NATOM*KPAD];
__device__ float g_cur[NATOM*DD];
__device__ float g_ctx[NATOM*DD];
__device__ float g_wsum[NATOM*DD];
__device__ float g_wtot[NATOM];
__device__ float g_concat[NROWN*KPAD];
__device__ float g_nei0[NROWN*DD];
__device__ float g_gi[NATOM*D3];
__device__ float g_gh[NATOM*D3];
__device__ float g_s2[NATOM];
__device__ float g_mol[BDIM*DD];
__device__ float g_actmol[BDIM*DD];
__device__ float g_mwsum[BDIM*DD];
__device__ float g_mwtot[BDIM];
__device__ float g_mctx[BDIM*DD];
__device__ float g_mgi[BDIM*D3];
__device__ float g_mgh[BDIM*D3];

// ---------------- helpers ----------------
__device__ __forceinline__ float warpsum(float v) {
    #pragma unroll
    for (int o = 16; o > 0; o >>= 1) v += __shfl_down_sync(0xffffffffu, v, o);
    return v;
}
__device__ __forceinline__ float lrelu(float x) { return x > 0.f ? x : 0.01f * x; }
__device__ __forceinline__ float eluf(float x)  { return x > 0.f ? x : expm1f(x); }
__device__ __forceinline__ float sigm(float x)  { return 1.f / (1.f + expf(-x)); }

__device__ __forceinline__ u64 splat2(float x) {
    u64 r; asm("mov.b64 %0, {%1, %1};" : "=l"(r) : "f"(x)); return r;
}
__device__ __forceinline__ void fma2(u64& d, u64 a, u64 b) {
    asm("fma.rn.f32x2 %0, %1, %2, %0;" : "+l"(d) : "l"(a), "l"(b));
}
__device__ __forceinline__ void unpack2(u64 v, float& lo, float& hi) {
    asm("mov.b64 {%0, %1}, %2;" : "=f"(lo), "=f"(hi) : "l"(v));
}

// =====================================================================
// Packed-fp32 SGEMM: C[M,N] = act(A[M,K](lda) @ B + rs[m]*bias)
// TRANSB=0: B[K,N] row-major.  TRANSB=1: B[N,K] row-major.
// ACT: 0 none, 1 lrelu, 2 elu. rowscale: per-row bias scale (null -> 1).
// BM=BN=128, BK=8, 256 threads, 8x8 microtile, f32x2 FMA, double-buffered.
// =====================================================================
template<int TRANSB, int ACT>
__global__ void __launch_bounds__(256, 2) gemm2_kernel(
    const float* __restrict__ A, int lda,
    const float* __restrict__ Bm,
    const float* __restrict__ bias,
    const float* __restrict__ rowscale,
    float* __restrict__ C,
    int M, int N, int K)
{
    __shared__ float As[2][8 * 132];
    __shared__ float Bs[2][8 * 132];

    const int tid = threadIdx.x;
    const int tx = tid & 15;
    const int ty = tid >> 4;
    const int bn0 = blockIdx.x * 128;
    const int bm0 = blockIdx.y * 128;
    const int m0 = ty * 8;
    const int n0 = tx * 8;

    const int ar  = tid >> 1;
    const int akc = (tid & 1) * 4;
    const int b_nr  = tid >> 1;
    const int b_kc  = (tid & 1) * 4;
    const int b_kr  = tid >> 5;
    const int b_nc  = (tid & 31) * 4;

    const int ntiles = (K + 7) >> 3;
    float4 aS, bS;

    u64 acc[8][4];
    #pragma unroll
    for (int i = 0; i < 8; i++)
        #pragma unroll
        for (int j = 0; j < 4; j++) acc[i][j] = 0ull;

    {
        const int k0 = 0;
        aS = *reinterpret_cast<const float4*>(A + (size_t)(bm0 + ar) * lda + k0 + akc);
        if (TRANSB) {
            int n = bn0 + b_nr;
            bS = (n < N) ? *reinterpret_cast<const float4*>(Bm + (size_t)n * K + k0 + b_kc)
                         : make_float4(0.f, 0.f, 0.f, 0.f);
        } else {
            int k = k0 + b_kr, n = bn0 + b_nc;
            bS = (k < K && n < N) ? *reinterpret_cast<const float4*>(Bm + (size_t)k * N + n)
                                  : make_float4(0.f, 0.f, 0.f, 0.f);
        }
        As[0][(akc + 0) * 132 + ar] = aS.x;
        As[0][(akc + 1) * 132 + ar] = aS.y;
        As[0][(akc + 2) * 132 + ar] = aS.z;
        As[0][(akc + 3) * 132 + ar] = aS.w;
        if (TRANSB) {
            Bs[0][(b_kc + 0) * 132 + b_nr] = bS.x;
            Bs[0][(b_kc + 1) * 132 + b_nr] = bS.y;
            Bs[0][(b_kc + 2) * 132 + b_nr] = bS.z;
            Bs[0][(b_kc + 3) * 132 + b_nr] = bS.w;
        } else {
            *reinterpret_cast<float4*>(&Bs[0][b_kr * 132 + b_nc]) = bS;
        }
    }
    __syncthreads();

    for (int t = 0; t < ntiles; t++) {
        const int cur = t & 1;
        if (t + 1 < ntiles) {
            const int k0 = (t + 1) << 3;
            aS = *reinterpret_cast<const float4*>(A + (size_t)(bm0 + ar) * lda + k0 + akc);
            if (TRANSB) {
                int n = bn0 + b_nr;
                bS = (n < N) ? *reinterpret_cast<const float4*>(Bm + (size_t)n * K + k0 + b_kc)
                             : make_float4(0.f, 0.f, 0.f, 0.f);
            } else {
                int k = k0 + b_kr, n = bn0 + b_nc;
                bS = (k < K && n < N) ? *reinterpret_cast<const float4*>(Bm + (size_t)k * N + n)
                                      : make_float4(0.f, 0.f, 0.f, 0.f);
            }
        }

        #pragma unroll
        for (int kk = 0; kk < 8; kk++) {
            const float* arow = &As[cur][kk * 132 + m0];
            float4 a03 = *reinterpret_cast<const float4*>(arow);
            float4 a47 = *reinterpret_cast<const float4*>(arow + 4);
            const u64* brow = reinterpret_cast<const u64*>(&Bs[cur][kk * 132 + n0]);
            u64 b2[4];
            #pragma unroll
            for (int j = 0; j < 4; j++) b2[j] = brow[j];
            u64 a2[8];
            a2[0] = splat2(a03.x); a2[1] = splat2(a03.y);
            a2[2] = splat2(a03.z); a2[3] = splat2(a03.w);
            a2[4] = splat2(a47.x); a2[5] = splat2(a47.y);
            a2[6] = splat2(a47.z); a2[7] = splat2(a47.w);
            #pragma unroll
            for (int i = 0; i < 8; i++)
                #pragma unroll
                for (int j = 0; j < 4; j++)
                    fma2(acc[i][j], a2[i], b2[j]);
        }

        if (t + 1 < ntiles) {
            const int nxt = cur ^ 1;
            As[nxt][(akc + 0) * 132 + ar] = aS.x;
            As[nxt][(akc + 1) * 132 + ar] = aS.y;
            As[nxt][(akc + 2) * 132 + ar] = aS.z;
            As[nxt][(akc + 3) * 132 + ar] = aS.w;
            if (TRANSB) {
                Bs[nxt][(b_kc + 0) * 132 + b_nr] = bS.x;
                Bs[nxt][(b_kc + 1) * 132 + b_nr] = bS.y;
                Bs[nxt][(b_kc + 2) * 132 + b_nr] = bS.z;
                Bs[nxt][(b_kc + 3) * 132 + b_nr] = bS.w;
            } else {
                *reinterpret_cast<float4*>(&Bs[nxt][b_kr * 132 + b_nc]) = bS;
            }
        }
        __syncthreads();
    }

    float bvals[8];
    #pragma unroll
    for (int j = 0; j < 8; j++) {
        int n = bn0 + n0 + j;
        bvals[j] = (bias && n < N) ? bias[n] : 0.f;
    }
    #pragma unroll
    for (int i = 0; i < 8; i++) {
        int m = bm0 + m0 + i;
        if (m >= M) continue;
        float rs = rowscale ? rowscale[m] : 1.f;
        float* crow = C + (size_t)m * N;
        #pragma unroll
        for (int j = 0; j < 4; j++) {
            float lo, hi; unpack2(acc[i][j], lo, hi);
            int n = bn0 + n0 + 2 * j;
            if (n < N) {
                float v = lo + rs * bvals[2 * j];
                if (ACT == 1) v = lrelu(v);
                if (ACT == 2) v = eluf(v);
                crow[n] = v;
            }
            if (n + 1 < N) {
                float v = hi + rs * bvals[2 * j + 1];
                if (ACT == 1) v = lrelu(v);
                if (ACT == 2) v = eluf(v);
                crow[n + 1] = v;
            }
        }
    }
}

// ---------------- pad atom_list [NATOM,39] -> [NATOM,64] ----------------
__global__ void pad_atom_kernel(const float* __restrict__ atom_list, float* __restrict__ out)
{
    int i = blockIdx.x * blockDim.x + threadIdx.x;
    if (i >= NATOM * KPAD) return;
    int row = i >> 6;
    int f = i & 63;
    out[i] = (f < FAA) ? atom_list[row * FAA + f] : 0.f;
}

// ---------------- build concat(atom_nei, bond_nei) [NROWN, 64] padded ----------------
__global__ void build_concat(const float* __restrict__ atom_list,
                             const float* __restrict__ bond_list,
                             const int* __restrict__ adeg,
                             const int* __restrict__ bdeg,
                             float* __restrict__ out)
{
    int i = blockIdx.x * blockDim.x + threadIdx.x;
    if (i >= NROWN * KPAD) return;
    int row = i >> 6;
    int f = i & 63;
    int b = row / (LDIM * NNEI);
    float v = 0.f;
    if (f < FAA) {
        int a = adeg[row];
        v = atom_list[((size_t)b * LDIM + a) * FAA + f];
    } else if (f < FC) {
        int bd = bdeg[row];
        v = bond_list[((size_t)b * MBOND + bd) * FBB + (f - FAA)];
    }
    out[i] = v;
}

// ---------------- attention: softmax weights + weighted neighbor sum ----------------
// Outputs wsum[atom, D] = sum_n w_n * nei_n   and  wtot[atom] = sum_n w_n.
// firstRound: nei rows from neiBuf [NROWN, D]; else nei = gather(cur).
__global__ void ctx_kernel(const float* __restrict__ cur,
                           const float* __restrict__ neiBuf,
                           const int* __restrict__ adeg,
                           const float* __restrict__ Wal,
                           const float* __restrict__ bal,
                           float* __restrict__ wsum,
                           float* __restrict__ wtot,
                           int firstRound)
{
    const int atom = blockIdx.x;
    const int b = atom / LDIM;
    const int tid = threadIdx.x;
    const int lane = tid & 31;

    __shared__ float curS[DD];
    __shared__ float neiS[NNEI][DD];
    __shared__ float red[NNEI + 1];
    __shared__ int idxS[NNEI];

    if (tid <= NNEI) red[tid] = 0.f;
    if (tid < NNEI) idxS[tid] = adeg[atom * NNEI + tid];
    for (int d = tid; d < DD; d += 256) curS[d] = cur[(size_t)atom * DD + d];
    __syncthreads();

    // stage neighbor rows in smem
    #pragma unroll
    for (int n = 0; n < NNEI; n++) {
        const float* src = firstRound ? (neiBuf + ((size_t)atom * NNEI + n) * DD)
                                      : (cur + ((size_t)(b * LDIM + idxS[n])) * DD);
        for (int d = tid; d < DD; d += 256) neiS[n][d] = src[d];
    }
    __syncthreads();

    float p[NNEI + 1];
    #pragma unroll
    for (int n = 0; n <= NNEI; n++) p[n] = 0.f;
    for (int d = tid; d < DD; d += 256) {
        float a1 = Wal[d];
        float a2 = Wal[DD + d];
        p[NNEI] += a1 * curS[d];
        #pragma unroll
        for (int n = 0; n < NNEI; n++) p[n] += a2 * neiS[n][d];
    }
    #pragma unroll
    for (int n = 0; n <= NNEI; n++) {
        float s = warpsum(p[n]);
        if (lane == 0) atomicAdd(&red[n], s);
    }
    __syncthreads();

    float dtop = red[NNEI];
    float bb = bal[0];
    float sc[NNEI];
    float msk[NNEI];
    float mx = -1e30f;
    #pragma unroll
    for (int n = 0; n < NNEI; n++) {
        float a = lrelu(dtop + red[n] + bb);
        bool pad = (idxS[n] == LDIM - 1);
        msk[n] = pad ? 0.f : 1.f;
        a += pad ? NEGV : 0.f;
        sc[n] = a;
        mx = fmaxf(mx, a);
    }
    float sum = 0.f;
    float w[NNEI];
    #pragma unroll
    for (int n = 0; n < NNEI; n++) { w[n] = expf(sc[n] - mx); sum += w[n]; }
    float inv = 1.f / sum;
    float wt = 0.f;
    #pragma unroll
    for (int n = 0; n < NNEI; n++) { w[n] = w[n] * inv * msk[n]; wt += w[n]; }

    for (int d = tid; d < DD; d += 256) {
        float s = 0.f;
        #pragma unroll
        for (int n = 0; n < NNEI; n++) s += w[n] * neiS[n][d];
        wsum[(size_t)atom * DD + d] = s;
    }
    if (tid == 0) wtot[atom] = wt;
}

// ---------------- GRU combine ----------------
__global__ void gru_combine(const float* __restrict__ gi, const float* __restrict__ gh,
                            const float* __restrict__ h,
                            float* __restrict__ hOut, float* __restrict__ actOut, int Mrows)
{
    int i = blockIdx.x * blockDim.x + threadIdx.x;
    if (i >= Mrows * DD) return;
    int m = i / DD;
    int d = i - m * DD;
    const float* gim = gi + (size_t)m * D3;
    const float* ghm = gh + (size_t)m * D3;
    float r = sigm(gim[d] + ghm[d]);
    float z = sigm(gim[DD + d] + ghm[DD + d]);
    float n = tanhf(gim[2 * DD + d] + r * ghm[2 * DD + d]);
    float hv = h[i];
    float hn = (1.f - z) * n + z * hv;
    hOut[i] = hn;
    actOut[i] = hn > 0.f ? hn : 0.f;
}

// ---------------- mol prep: masked sum + per-atom s2 dot ----------------
__global__ void molprep_kernel(const float* __restrict__ cur, const float* __restrict__ amask,
                               const float* __restrict__ Wma,
                               float* __restrict__ mol, float* __restrict__ actmol,
                               float* __restrict__ s2)
{
    int b = blockIdx.x;
    int tid = threadIdx.x;
    // phase 1: column sums
    for (int d = tid; d < DD; d += 256) {
        float s = 0.f;
        for (int l = 0; l < LDIM; l++)
            s += cur[((size_t)b * LDIM + l) * DD + d] * amask[b * LDIM + l];
        mol[b * DD + d] = s;
        actmol[b * DD + d] = s > 0.f ? s : 0.f;
    }
    // phase 2: per-atom dot with Wma[DD:2DD]
    int w = tid >> 5;
    int lane = tid & 31;
    for (int l = w; l < LDIM; l += 8) {
        float p = 0.f;
        const float* row = cur + ((size_t)b * LDIM + l) * DD;
        for (int d = lane; d < DD; d += 32) p += row[d] * Wma[DD + d];
        p = warpsum(p);
        if (lane == 0) s2[b * LDIM + l] = p;
    }
}

// ---------------- mol attention: weights + weighted atom sum ----------------
__global__ void molctx_kernel(const float* __restrict__ actmol,
                              const float* __restrict__ cur,
                              const float* __restrict__ s2,
                              const float* __restrict__ amask,
                              const float* __restrict__ Wma,
                              const float* __restrict__ bma,
                              float* __restrict__ mwsum,
                              float* __restrict__ mwtot)
{
    int b = blockIdx.x;
    int tid = threadIdx.x;
    int lane = tid & 31;
    __shared__ float redv;
    __shared__ float sc[LDIM];
    __shared__ float wS[LDIM];
    if (tid == 0) redv = 0.f;
    __syncthreads();

    float p = 0.f;
    for (int d = tid; d < DD; d += 256) p += actmol[b * DD + d] * Wma[d];
    p = warpsum(p);
    if (lane == 0) atomicAdd(&redv, p);
    __syncthreads();

    if (tid < LDIM) {
        float a = lrelu(redv + s2[b * LDIM + tid] + bma[0]);
        if (amask[b * LDIM + tid] == 0.f) a += NEGV;
        sc[tid] = a;
    }
    __syncthreads();

    float mx = -1e30f;
    for (int l = 0; l < LDIM; l++) mx = fmaxf(mx, sc[l]);
    float sum = 0.f;
    for (int l = 0; l < LDIM; l++) sum += expf(sc[l] - mx);
    float inv = 1.f / sum;
    if (tid < LDIM) wS[tid] = expf(sc[tid] - mx) * inv * amask[b * LDIM + tid];
    __syncthreads();

    for (int d = tid; d < DD; d += 256) {
        float s = 0.f;
        for (int l = 0; l < LDIM; l++)
            s += wS[l] * cur[((size_t)b * LDIM + l) * DD + d];
        mwsum[b * DD + d] = s;
    }
    if (tid == 0) {
        float wt = 0.f;
        for (int l = 0; l < LDIM; l++) wt += wS[l];
        mwtot[b] = wt;
    }
}

// ---------------- final projection ----------------
__global__ void final_kernel(const float* __restrict__ mol,
                             const float* __restrict__ Wm, const float* __restrict__ bm,
                             const float* __restrict__ Wo, const float* __restrict__ bo,
                             float* __restrict__ out)
{
    int b = blockIdx.x;
    int tid = threadIdx.x;
    int lane = tid & 31;
    __shared__ float featS[D2];
    __shared__ float ws[8];
    for (int j = tid; j < D2; j += 256)
        featS[j] = (j < DD) ? mol[b * DD + j] : (mol[b * DD + j - DD] + (float)(RR - 2));
    __syncthreads();
    float p = 0.f;
    for (int d = tid; d < DD; d += 256) {
        float s = bm[d];
        for (int j = 0; j < D2; j++) s += featS[j] * Wm[j * DD + d];
        p += s * Wo[d];
    }
    p = warpsum(p);
    if (lane == 0) ws[tid >> 5] = p;
    __syncthreads();
    if (tid == 0) {
        float t = 0.f;
        for (int i = 0; i < 8; i++) t += ws[i];
        out[b] = t + bo[0];
    }
}

// ---------------- host-side GEMM dispatch ----------------
static void gemm(const float* A, int lda, const float* Bm, const float* bias,
                 const float* rowscale, float* C,
                 int M, int N, int K, int transB, int act)
{
    dim3 g((N + 127) / 128, (M + 127) / 128), blk(256);
    if (transB) {
        if (act == 1)      gemm2_kernel<1, 1><<<g, blk>>>(A, lda, Bm, bias, rowscale, C, M, N, K);
        else if (act == 2) gemm2_kernel<1, 2><<<g, blk>>>(A, lda, Bm, bias, rowscale, C, M, N, K);
        else               gemm2_kernel<1, 0><<<g, blk>>>(A, lda, Bm, bias, rowscale, C, M, N, K);
    } else {
        if (act == 1)      gemm2_kernel<0, 1><<<g, blk>>>(A, lda, Bm, bias, rowscale, C, M, N, K);
        else if (act == 2) gemm2_kernel<0, 2><<<g, blk>>>(A, lda, Bm, bias, rowscale, C, M, N, K);
        else               gemm2_kernel<0, 0><<<g, blk>>>(A, lda, Bm, bias, rowscale, C, M, N, K);
    }
}

extern "C" void kernel_launch(void* const* d_in, const int* in_sizes, int n_in,
                              void* d_out, int out_size)
{
    const float* atom_list   = (const float*)d_in[0];
    const float* bond_list   = (const float*)d_in[1];
    const int*   adeg        = (const int*)d_in[2];
    const int*   bdeg        = (const int*)d_in[3];
    const float* amask       = (const float*)d_in[4];
    const float* W_atom      = (const float*)d_in[5];
    const float* b_atom      = (const float*)d_in[6];
    const float* W_nei       = (const float*)d_in[7];
    const float* b_nei       = (const float*)d_in[8];
    const float* W_align     = (const float*)d_in[9];
    const float* b_align     = (const float*)d_in[10];
    const float* W_attend    = (const float*)d_in[11];
    const float* b_attend    = (const float*)d_in[12];
    const float* Wih         = (const float*)d_in[13];
    const float* Whh         = (const float*)d_in[14];
    const float* bih         = (const float*)d_in[15];
    const float* bhh         = (const float*)d_in[16];
    const float* W_mol_align = (const float*)d_in[17];
    const float* b_mol_align = (const float*)d_in[18];
    const float* W_mol_att   = (const float*)d_in[19];
    const float* b_mol_att   = (const float*)d_in[20];
    const float* mWih        = (const float*)d_in[21];
    const float* mWhh        = (const float*)d_in[22];
    const float* mbih        = (const float*)d_in[23];
    const float* mbhh        = (const float*)d_in[24];
    const float* W_metric    = (const float*)d_in[25];
    const float* b_metric    = (const float*)d_in[26];
    const float* W_out       = (const float*)d_in[27];
    const float* b_out       = (const float*)d_in[28];

    float *atomfeat, *atompad, *cur, *ctx, *wsum, *wtot, *concat, *nei0, *gi, *gh;
    float *s2, *mol, *actmol, *mwsum, *mwtot, *mctx, *mgi, *mgh;
    cudaGetSymbolAddress((void**)&atomfeat, g_atomfeat);
    cudaGetSymbolAddress((void**)&atompad, g_atompad);
    cudaGetSymbolAddress((void**)&cur, g_cur);
    cudaGetSymbolAddress((void**)&ctx, g_ctx);
    cudaGetSymbolAddress((void**)&wsum, g_wsum);
    cudaGetSymbolAddress((void**)&wtot, g_wtot);
    cudaGetSymbolAddress((void**)&concat, g_concat);
    cudaGetSymbolAddress((void**)&nei0, g_nei0);
    cudaGetSymbolAddress((void**)&gi, g_gi);
    cudaGetSymbolAddress((void**)&gh, g_gh);
    cudaGetSymbolAddress((void**)&s2, g_s2);
    cudaGetSymbolAddress((void**)&mol, g_mol);
    cudaGetSymbolAddress((void**)&actmol, g_actmol);
    cudaGetSymbolAddress((void**)&mwsum, g_mwsum);
    cudaGetSymbolAddress((void**)&mwtot, g_mwtot);
    cudaGetSymbolAddress((void**)&mctx, g_mctx);
    cudaGetSymbolAddress((void**)&mgi, g_mgi);
    cudaGetSymbolAddress((void**)&mgh, g_mgh);

    float* h = atomfeat;   // h aliases atomfeat; updated in place by gru_combine

    // 1) atom_feature = lrelu(atom_list @ W_atom + b_atom)
    pad_atom_kernel<<<(NATOM * KPAD + 255) / 256, 256>>>(atom_list, atompad);
    gemm(atompad, KPAD, W_atom, b_atom, nullptr, atomfeat, NATOM, DD, FAA, 0, 1);

    // 2) nei0 = lrelu(concat(atom_nei, bond_nei) @ W_nei + b_nei)
    build_concat<<<(NROWN * KPAD + 255) / 256, 256>>>(atom_list, bond_list, adeg, bdeg, concat);
    gemm(concat, KPAD, W_nei, b_nei, nullptr, nei0, NROWN, DD, FC, 0, 1);

    // 3) atom GRU rounds: ctx = elu(wsum @ W_attend + wtot*b_attend)
    for (int r = 0; r < RR; r++) {
        const float* curp = (r == 0) ? atomfeat : cur;
        ctx_kernel<<<NATOM, 256>>>(curp, (r == 0) ? nei0 : nullptr, adeg,
                                   W_align + (size_t)r * D2, b_align + r,
                                   wsum, wtot, (r == 0) ? 1 : 0);
        gemm(wsum, DD, W_attend + (size_t)r * DD * DD, b_attend + r * DD, wtot,
             ctx, NATOM, DD, DD, 0, 2);
        gemm(ctx, DD, Wih + (size_t)r * D3 * DD, bih + r * D3, nullptr, gi, NATOM, D3, DD, 1, 0);
        gemm(h,   DD, Whh + (size_t)r * D3 * DD, bhh + r * D3, nullptr, gh, NATOM, D3, DD, 1, 0);
        gru_combine<<<(NATOM * DD + 255) / 256, 256>>>(gi, gh, h, h, cur, NATOM);
    }

    // 4) mol phase
    molprep_kernel<<<BDIM, 256>>>(cur, amask, W_mol_align, mol, actmol, s2);
    for (int t = 0; t < TTI; t++) {
        molctx_kernel<<<BDIM, 256>>>(actmol, cur, s2, amask, W_mol_align, b_mol_align,
                                     mwsum, mwtot);
        gemm(mwsum, DD, W_mol_att, b_mol_att, mwtot, mctx, BDIM, DD, DD, 0, 2);
        gemm(mctx, DD, mWih, mbih, nullptr, mgi, BDIM, D3, DD, 1, 0);
        gemm(mol,  DD, mWhh, mbhh, nullptr, mgh, BDIM, D3, DD, 1, 0);
        gru_combine<<<(BDIM * DD + 255) / 256, 256>>>(mgi, mgh, mol, mol, actmol, BDIM);
    }

    // 5) final projection
    final_kernel<<<BDIM, 256>>>(mol, W_metric, b_metric, W_out, b_out, (float*)d_out);
}

// round 7
// speedup vs baseline: 1.6275x; 1.2668x over previous
#include <cuda_runtime.h>
#include <math.h>
#include <stdint.h>

typedef unsigned long long u64;

#define BDIM 128
#define LDIM 128
#define NNEI 6
#define FAA 39
#define FBB 10
#define FC 49
#define DD 200
#define D2 400
#define D3 600
#define RR 3
#define TTI 2
#define MBOND 256
#define NEGV -9e8f
#define NATOM (BDIM*LDIM)    /* 16384 */
#define NROWN (NATOM*NNEI)   /* 98304 */
#define KPAD 64
#define KP 224               /* padded K for K-major weight buffers */

// ---------------- device scratch (static, no allocation) ----------------
__device__ float g_atomfeat[NATOM*DD];   // also serves as h (updated in place)
__device__ float g_atompad[NATOM*KPAD];
__device__ float g_cur[NATOM*DD];
__device__ float g_ctx[NATOM*DD];
__device__ float g_wsum[NATOM*DD];
__device__ float g_wtot[NATOM];
__device__ float g_concat[NROWN*KPAD];
__device__ float g_nei0[NROWN*DD];
__device__ float g_gi[NATOM*D3];
__device__ float g_gh[NATOM*D3];
__device__ float g_s2[NATOM];
__device__ float g_mol[BDIM*DD];
__device__ float g_actmol[BDIM*DD];
__device__ float g_mwsum[BDIM*DD];
__device__ float g_mwtot[BDIM];
__device__ float g_mctx[BDIM*DD];
__device__ float g_mgi[BDIM*D3];
__device__ float g_mgh[BDIM*D3];
// K-major padded weights [N, KP]
__device__ float g_WT_atom[200*KP];
__device__ float g_WT_nei[200*KP];
__device__ float g_WT_att[3*200*KP];
__device__ float g_WT_molatt[200*KP];
__device__ float g_Wih_p[3*600*KP];
__device__ float g_Whh_p[3*600*KP];
__device__ float g_mWih_p[600*KP];
__device__ float g_mWhh_p[600*KP];

// ---------------- helpers ----------------
__device__ __forceinline__ float warpsum(float v) {
    #pragma unroll
    for (int o = 16; o > 0; o >>= 1) v += __shfl_down_sync(0xffffffffu, v, o);
    return v;
}
__device__ __forceinline__ float lrelu(float x) { return x > 0.f ? x : 0.01f * x; }
__device__ __forceinline__ float eluf(float x)  { return x > 0.f ? x : expm1f(x); }
__device__ __forceinline__ float sigm(float x)  { return 1.f / (1.f + expf(-x)); }

__device__ __forceinline__ uint32_t to_tf32(float x) {
    uint32_t r; asm("cvt.rna.tf32.f32 %0, %1;" : "=r"(r) : "f"(x)); return r;
}

#define MMA8(c, a, b) \
    asm volatile("mma.sync.aligned.m16n8k8.row.col.f32.tf32.tf32.f32 " \
        "{%0,%1,%2,%3}, {%4,%5,%6,%7}, {%8,%9}, {%0,%1,%2,%3};" \
        : "+f"((c)[0]), "+f"((c)[1]), "+f"((c)[2]), "+f"((c)[3]) \
        : "r"((a)[0]), "r"((a)[1]), "r"((a)[2]), "r"((a)[3]), \
          "r"((b)[0]), "r"((b)[1]))

// =====================================================================
// Split-tf32 tensor GEMM: C[M,Ntot] = act(A[M,K](lda) @ WT^T + rs[m]*bias)
// WT: [Ntot, KP] K-major, zero-padded beyond K. Each x split hi+lo (tf32),
// accumulate hi*hi + hi*lo + lo*hi in fp32 -> ~fp32 accuracy.
// BM=128, BN=64, BK=16. 256 threads = 8 warps (4m x 2n), warp tile 32x32.
// =====================================================================
__global__ __launch_bounds__(256) void tf32gemm_kernel(
    const float* __restrict__ A, int lda, int K,
    const float* __restrict__ WT,
    const float* __restrict__ bias,
    const float* __restrict__ rowscale,
    float* __restrict__ C, int M, int Ntot, int act)
{
    __shared__ float Ah[16][136], Al[16][136];
    __shared__ float Bh[16][72],  Bl[16][72];

    const int tid = threadIdx.x;
    const int wid = tid >> 5;
    const int lane = tid & 31;
    const int gid = lane >> 2;      // 0..7
    const int tg = lane & 3;        // 0..3
    const int bm0 = blockIdx.x * 128;
    const int bn0 = blockIdx.y * 64;
    const int wm = (wid & 3) * 32;
    const int wn = (wid >> 2) * 32;

    float c[2][4][4];
    #pragma unroll
    for (int mt = 0; mt < 2; mt++)
        #pragma unroll
        for (int nt = 0; nt < 4; nt++)
            #pragma unroll
            for (int q = 0; q < 4; q++) c[mt][nt][q] = 0.f;

    const int nch = (K + 15) >> 4;
    for (int ch = 0; ch < nch; ch++) {
        const int k0 = ch << 4;
        // stage A tile: 128 rows x 16 k (512 float4, 2/thread)
        #pragma unroll
        for (int it = 0; it < 2; it++) {
            int i = tid + it * 256;
            int r = i >> 2, c4 = (i & 3) << 2;
            int k = k0 + c4;
            float4 v = make_float4(0.f, 0.f, 0.f, 0.f);
            if (k < K) v = *reinterpret_cast<const float4*>(A + (size_t)(bm0 + r) * lda + k);
            const float* vp = &v.x;
            #pragma unroll
            for (int j = 0; j < 4; j++) {
                float x = vp[j];
                uint32_t hb = to_tf32(x);
                float hf = __uint_as_float(hb);
                uint32_t lb = to_tf32(x - hf);
                Ah[c4 + j][r] = hf;
                Al[c4 + j][r] = __uint_as_float(lb);
            }
        }
        // stage B tile: 64 rows x 16 k (256 float4, 1/thread)
        {
            int r = tid >> 2, c4 = (tid & 3) << 2;
            int n = bn0 + r;
            float4 v = make_float4(0.f, 0.f, 0.f, 0.f);
            if (n < Ntot) v = *reinterpret_cast<const float4*>(WT + (size_t)n * KP + k0 + c4);
            const float* vp = &v.x;
            #pragma unroll
            for (int j = 0; j < 4; j++) {
                float x = vp[j];
                uint32_t hb = to_tf32(x);
                float hf = __uint_as_float(hb);
                uint32_t lb = to_tf32(x - hf);
                Bh[c4 + j][r] = hf;
                Bl[c4 + j][r] = __uint_as_float(lb);
            }
        }
        __syncthreads();

        #pragma unroll
        for (int ks = 0; ks < 2; ks++) {
            const int kb = ks * 8;
            uint32_t ah[2][4], al[2][4];
            #pragma unroll
            for (int mt = 0; mt < 2; mt++) {
                int mr = wm + mt * 16;
                ah[mt][0] = __float_as_uint(Ah[kb + tg][mr + gid]);
                ah[mt][1] = __float_as_uint(Ah[kb + tg][mr + gid + 8]);
                ah[mt][2] = __float_as_uint(Ah[kb + tg + 4][mr + gid]);
                ah[mt][3] = __float_as_uint(Ah[kb + tg + 4][mr + gid + 8]);
                al[mt][0] = __float_as_uint(Al[kb + tg][mr + gid]);
                al[mt][1] = __float_as_uint(Al[kb + tg][mr + gid + 8]);
                al[mt][2] = __float_as_uint(Al[kb + tg + 4][mr + gid]);
                al[mt][3] = __float_as_uint(Al[kb + tg + 4][mr + gid + 8]);
            }
            uint32_t bh[4][2], bl[4][2];
            #pragma unroll
            for (int nt = 0; nt < 4; nt++) {
                int nc = wn + nt * 8 + gid;
                bh[nt][0] = __float_as_uint(Bh[kb + tg][nc]);
                bh[nt][1] = __float_as_uint(Bh[kb + tg + 4][nc]);
                bl[nt][0] = __float_as_uint(Bl[kb + tg][nc]);
                bl[nt][1] = __float_as_uint(Bl[kb + tg + 4][nc]);
            }
            #pragma unroll
            for (int mt = 0; mt < 2; mt++)
                #pragma unroll
                for (int nt = 0; nt < 4; nt++) {
                    MMA8(c[mt][nt], ah[mt], bh[nt]);
                    MMA8(c[mt][nt], ah[mt], bl[nt]);
                    MMA8(c[mt][nt], al[mt], bh[nt]);
                }
        }
        __syncthreads();
    }

    // epilogue
    #pragma unroll
    for (int mt = 0; mt < 2; mt++) {
        #pragma unroll
        for (int half = 0; half < 2; half++) {
            int m = bm0 + wm + mt * 16 + gid + half * 8;
            float rs = rowscale ? rowscale[m] : 1.f;
            float* crow = C + (size_t)m * Ntot;
            #pragma unroll
            for (int nt = 0; nt < 4; nt++) {
                int n = bn0 + wn + nt * 8 + 2 * tg;
                float v0 = c[mt][nt][half * 2 + 0];
                float v1 = c[mt][nt][half * 2 + 1];
                if (n < Ntot) {
                    float v = v0 + rs * (bias ? bias[n] : 0.f);
                    if (act == 1) v = lrelu(v);
                    else if (act == 2) v = eluf(v);
                    crow[n] = v;
                }
                if (n + 1 < Ntot) {
                    float v = v1 + rs * (bias ? bias[n + 1] : 0.f);
                    if (act == 1) v = lrelu(v);
                    else if (act == 2) v = eluf(v);
                    crow[n + 1] = v;
                }
            }
        }
    }
}

// ---------------- weight prep: pad [NT,K] -> [NT,KP] ----------------
__global__ void prep_pad(const float* __restrict__ in, float* __restrict__ out, int NT, int K)
{
    int i = blockIdx.x * 256 + threadIdx.x;
    if (i >= NT * KP) return;
    int n = i / KP, k = i - n * KP;
    out[i] = (k < K) ? in[(size_t)n * K + k] : 0.f;
}

// ---------------- weight prep: transpose [R,K,N] -> [R,N,KP] ----------------
__global__ void prep_trans(const float* __restrict__ in, float* __restrict__ out, int R, int K, int N)
{
    int i = blockIdx.x * 256 + threadIdx.x;
    if (i >= R * N * KP) return;
    int k = i % KP;
    int rn = i / KP;
    int n = rn % N;
    int r = rn / N;
    out[i] = (k < K) ? in[((size_t)r * K + k) * N + n] : 0.f;
}

// ---------------- pad atom_list [NATOM,39] -> [NATOM,64] ----------------
__global__ void pad_atom_kernel(const float* __restrict__ atom_list, float* __restrict__ out)
{
    int i = blockIdx.x * blockDim.x + threadIdx.x;
    if (i >= NATOM * KPAD) return;
    int row = i >> 6;
    int f = i & 63;
    out[i] = (f < FAA) ? atom_list[row * FAA + f] : 0.f;
}

// ---------------- build concat(atom_nei, bond_nei) [NROWN, 64] padded ----------------
__global__ void build_concat(const float* __restrict__ atom_list,
                             const float* __restrict__ bond_list,
                             const int* __restrict__ adeg,
                             const int* __restrict__ bdeg,
                             float* __restrict__ out)
{
    int i = blockIdx.x * blockDim.x + threadIdx.x;
    if (i >= NROWN * KPAD) return;
    int row = i >> 6;
    int f = i & 63;
    int b = row / (LDIM * NNEI);
    float v = 0.f;
    if (f < FAA) {
        int a = adeg[row];
        v = atom_list[((size_t)b * LDIM + a) * FAA + f];
    } else if (f < FC) {
        int bd = bdeg[row];
        v = bond_list[((size_t)b * MBOND + bd) * FBB + (f - FAA)];
    }
    out[i] = v;
}

// ---------------- attention: softmax weights + weighted neighbor sum ----------------
__global__ void ctx_kernel(const float* __restrict__ cur,
                           const float* __restrict__ neiBuf,
                           const int* __restrict__ adeg,
                           const float* __restrict__ Wal,
                           const float* __restrict__ bal,
                           float* __restrict__ wsum,
                           float* __restrict__ wtot,
                           int firstRound)
{
    const int atom = blockIdx.x;
    const int b = atom / LDIM;
    const int tid = threadIdx.x;
    const int lane = tid & 31;

    __shared__ float curS[DD];
    __shared__ float neiS[NNEI][DD];
    __shared__ float red[NNEI + 1];
    __shared__ int idxS[NNEI];

    if (tid <= NNEI) red[tid] = 0.f;
    if (tid < NNEI) idxS[tid] = adeg[atom * NNEI + tid];
    for (int d = tid; d < DD; d += 256) curS[d] = cur[(size_t)atom * DD + d];
    __syncthreads();

    #pragma unroll
    for (int n = 0; n < NNEI; n++) {
        const float* src = firstRound ? (neiBuf + ((size_t)atom * NNEI + n) * DD)
                                      : (cur + ((size_t)(b * LDIM + idxS[n])) * DD);
        for (int d = tid; d < DD; d += 256) neiS[n][d] = src[d];
    }
    __syncthreads();

    float p[NNEI + 1];
    #pragma unroll
    for (int n = 0; n <= NNEI; n++) p[n] = 0.f;
    for (int d = tid; d < DD; d += 256) {
        float a1 = Wal[d];
        float a2 = Wal[DD + d];
        p[NNEI] += a1 * curS[d];
        #pragma unroll
        for (int n = 0; n < NNEI; n++) p[n] += a2 * neiS[n][d];
    }
    #pragma unroll
    for (int n = 0; n <= NNEI; n++) {
        float s = warpsum(p[n]);
        if (lane == 0) atomicAdd(&red[n], s);
    }
    __syncthreads();

    float dtop = red[NNEI];
    float bb = bal[0];
    float sc[NNEI];
    float msk[NNEI];
    float mx = -1e30f;
    #pragma unroll
    for (int n = 0; n < NNEI; n++) {
        float a = lrelu(dtop + red[n] + bb);
        bool pad = (idxS[n] == LDIM - 1);
        msk[n] = pad ? 0.f : 1.f;
        a += pad ? NEGV : 0.f;
        sc[n] = a;
        mx = fmaxf(mx, a);
    }
    float sum = 0.f;
    float w[NNEI];
    #pragma unroll
    for (int n = 0; n < NNEI; n++) { w[n] = expf(sc[n] - mx); sum += w[n]; }
    float inv = 1.f / sum;
    float wt = 0.f;
    #pragma unroll
    for (int n = 0; n < NNEI; n++) { w[n] = w[n] * inv * msk[n]; wt += w[n]; }

    for (int d = tid; d < DD; d += 256) {
        float s = 0.f;
        #pragma unroll
        for (int n = 0; n < NNEI; n++) s += w[n] * neiS[n][d];
        wsum[(size_t)atom * DD + d] = s;
    }
    if (tid == 0) wtot[atom] = wt;
}

// ---------------- GRU combine ----------------
__global__ void gru_combine(const float* __restrict__ gi, const float* __restrict__ gh,
                            const float* __restrict__ h,
                            float* __restrict__ hOut, float* __restrict__ actOut, int Mrows)
{
    int i = blockIdx.x * blockDim.x + threadIdx.x;
    if (i >= Mrows * DD) return;
    int m = i / DD;
    int d = i - m * DD;
    const float* gim = gi + (size_t)m * D3;
    const float* ghm = gh + (size_t)m * D3;
    float r = sigm(gim[d] + ghm[d]);
    float z = sigm(gim[DD + d] + ghm[DD + d]);
    float n = tanhf(gim[2 * DD + d] + r * ghm[2 * DD + d]);
    float hv = h[i];
    float hn = (1.f - z) * n + z * hv;
    hOut[i] = hn;
    actOut[i] = hn > 0.f ? hn : 0.f;
}

// ---------------- mol prep: masked sum + per-atom s2 dot ----------------
__global__ void molprep_kernel(const float* __restrict__ cur, const float* __restrict__ amask,
                               const float* __restrict__ Wma,
                               float* __restrict__ mol, float* __restrict__ actmol,
                               float* __restrict__ s2)
{
    int b = blockIdx.x;
    int tid = threadIdx.x;
    for (int d = tid; d < DD; d += 256) {
        float s = 0.f;
        for (int l = 0; l < LDIM; l++)
            s += cur[((size_t)b * LDIM + l) * DD + d] * amask[b * LDIM + l];
        mol[b * DD + d] = s;
        actmol[b * DD + d] = s > 0.f ? s : 0.f;
    }
    int w = tid >> 5;
    int lane = tid & 31;
    for (int l = w; l < LDIM; l += 8) {
        float p = 0.f;
        const float* row = cur + ((size_t)b * LDIM + l) * DD;
        for (int d = lane; d < DD; d += 32) p += row[d] * Wma[DD + d];
        p = warpsum(p);
        if (lane == 0) s2[b * LDIM + l] = p;
    }
}

// ---------------- mol attention: weights + weighted atom sum ----------------
__global__ void molctx_kernel(const float* __restrict__ actmol,
                              const float* __restrict__ cur,
                              const float* __restrict__ s2,
                              const float* __restrict__ amask,
                              const float* __restrict__ Wma,
                              const float* __restrict__ bma,
                              float* __restrict__ mwsum,
                              float* __restrict__ mwtot)
{
    int b = blockIdx.x;
    int tid = threadIdx.x;
    int lane = tid & 31;
    __shared__ float redv;
    __shared__ float sc[LDIM];
    __shared__ float wS[LDIM];
    if (tid == 0) redv = 0.f;
    __syncthreads();

    float p = 0.f;
    for (int d = tid; d < DD; d += 256) p += actmol[b * DD + d] * Wma[d];
    p = warpsum(p);
    if (lane == 0) atomicAdd(&redv, p);
    __syncthreads();

    if (tid < LDIM) {
        float a = lrelu(redv + s2[b * LDIM + tid] + bma[0]);
        if (amask[b * LDIM + tid] == 0.f) a += NEGV;
        sc[tid] = a;
    }
    __syncthreads();

    float mx = -1e30f;
    for (int l = 0; l < LDIM; l++) mx = fmaxf(mx, sc[l]);
    float sum = 0.f;
    for (int l = 0; l < LDIM; l++) sum += expf(sc[l] - mx);
    float inv = 1.f / sum;
    if (tid < LDIM) wS[tid] = expf(sc[tid] - mx) * inv * amask[b * LDIM + tid];
    __syncthreads();

    for (int d = tid; d < DD; d += 256) {
        float s = 0.f;
        for (int l = 0; l < LDIM; l++)
            s += wS[l] * cur[((size_t)b * LDIM + l) * DD + d];
        mwsum[b * DD + d] = s;
    }
    if (tid == 0) {
        float wt = 0.f;
        for (int l = 0; l < LDIM; l++) wt += wS[l];
        mwtot[b] = wt;
    }
}

// ---------------- final projection ----------------
__global__ void final_kernel(const float* __restrict__ mol,
                             const float* __restrict__ Wm, const float* __restrict__ bm,
                             const float* __restrict__ Wo, const float* __restrict__ bo,
                             float* __restrict__ out)
{
    int b = blockIdx.x;
    int tid = threadIdx.x;
    int lane = tid & 31;
    __shared__ float featS[D2];
    __shared__ float ws[8];
    for (int j = tid; j < D2; j += 256)
        featS[j] = (j < DD) ? mol[b * DD + j] : (mol[b * DD + j - DD] + (float)(RR - 2));
    __syncthreads();
    float p = 0.f;
    for (int d = tid; d < DD; d += 256) {
        float s = bm[d];
        for (int j = 0; j < D2; j++) s += featS[j] * Wm[j * DD + d];
        p += s * Wo[d];
    }
    p = warpsum(p);
    if (lane == 0) ws[tid >> 5] = p;
    __syncthreads();
    if (tid == 0) {
        float t = 0.f;
        for (int i = 0; i < 8; i++) t += ws[i];
        out[b] = t + bo[0];
    }
}

// ---------------- host-side tensor GEMM dispatch ----------------
static void tgemm(const float* A, int lda, int K, const float* WT,
                  const float* bias, const float* rowscale, float* C,
                  int M, int Ntot, int act)
{
    dim3 g(M / 128, (Ntot + 63) / 64);
    tf32gemm_kernel<<<g, 256>>>(A, lda, K, WT, bias, rowscale, C, M, Ntot, act);
}

extern "C" void kernel_launch(void* const* d_in, const int* in_sizes, int n_in,
                              void* d_out, int out_size)
{
    const float* atom_list   = (const float*)d_in[0];
    const float* bond_list   = (const float*)d_in[1];
    const int*   adeg        = (const int*)d_in[2];
    const int*   bdeg        = (const int*)d_in[3];
    const float* amask       = (const float*)d_in[4];
    const float* W_atom      = (const float*)d_in[5];
    const float* b_atom      = (const float*)d_in[6];
    const float* W_nei       = (const float*)d_in[7];
    const float* b_nei       = (const float*)d_in[8];
    const float* W_align     = (const float*)d_in[9];
    const float* b_align     = (const float*)d_in[10];
    const float* W_attend    = (const float*)d_in[11];
    const float* b_attend    = (const float*)d_in[12];
    const float* Wih         = (const float*)d_in[13];
    const float* Whh         = (const float*)d_in[14];
    const float* bih         = (const float*)d_in[15];
    const float* bhh         = (const float*)d_in[16];
    const float* W_mol_align = (const float*)d_in[17];
    const float* b_mol_align = (const float*)d_in[18];
    const float* W_mol_att   = (const float*)d_in[19];
    const float* b_mol_att   = (const float*)d_in[20];
    const float* mWih        = (const float*)d_in[21];
    const float* mWhh        = (const float*)d_in[22];
    const float* mbih        = (const float*)d_in[23];
    const float* mbhh        = (const float*)d_in[24];
    const float* W_metric    = (const float*)d_in[25];
    const float* b_metric    = (const float*)d_in[26];
    const float* W_out       = (const float*)d_in[27];
    const float* b_out       = (const float*)d_in[28];

    float *atomfeat, *atompad, *cur, *ctx, *wsum, *wtot, *concat, *nei0, *gi, *gh;
    float *s2, *mol, *actmol, *mwsum, *mwtot, *mctx, *mgi, *mgh;
    float *WT_atom, *WT_nei, *WT_att, *WT_molatt, *Wih_p, *Whh_p, *mWih_p, *mWhh_p;
    cudaGetSymbolAddress((void**)&atomfeat, g_atomfeat);
    cudaGetSymbolAddress((void**)&atompad, g_atompad);
    cudaGetSymbolAddress((void**)&cur, g_cur);
    cudaGetSymbolAddress((void**)&ctx, g_ctx);
    cudaGetSymbolAddress((void**)&wsum, g_wsum);
    cudaGetSymbolAddress((void**)&wtot, g_wtot);
    cudaGetSymbolAddress((void**)&concat, g_concat);
    cudaGetSymbolAddress((void**)&nei0, g_nei0);
    cudaGetSymbolAddress((void**)&gi, g_gi);
    cudaGetSymbolAddress((void**)&gh, g_gh);
    cudaGetSymbolAddress((void**)&s2, g_s2);
    cudaGetSymbolAddress((void**)&mol, g_mol);
    cudaGetSymbolAddress((void**)&actmol, g_actmol);
    cudaGetSymbolAddress((void**)&mwsum, g_mwsum);
    cudaGetSymbolAddress((void**)&mwtot, g_mwtot);
    cudaGetSymbolAddress((void**)&mctx, g_mctx);
    cudaGetSymbolAddress((void**)&mgi, g_mgi);
    cudaGetSymbolAddress((void**)&mgh, g_mgh);
    cudaGetSymbolAddress((void**)&WT_atom, g_WT_atom);
    cudaGetSymbolAddress((void**)&WT_nei, g_WT_nei);
    cudaGetSymbolAddress((void**)&WT_att, g_WT_att);
    cudaGetSymbolAddress((void**)&WT_molatt, g_WT_molatt);
    cudaGetSymbolAddress((void**)&Wih_p, g_Wih_p);
    cudaGetSymbolAddress((void**)&Whh_p, g_Whh_p);
    cudaGetSymbolAddress((void**)&mWih_p, g_mWih_p);
    cudaGetSymbolAddress((void**)&mWhh_p, g_mWhh_p);

    float* h = atomfeat;   // h aliases atomfeat; updated in place by gru_combine

    // 0) weight prep (pad/transpose to K-major [N, KP])
    {
        int n;
        n = 1800 * KP; prep_pad<<<(n + 255) / 256, 256>>>(Wih, Wih_p, 1800, DD);
        n = 1800 * KP; prep_pad<<<(n + 255) / 256, 256>>>(Whh, Whh_p, 1800, DD);
        n = 600 * KP;  prep_pad<<<(n + 255) / 256, 256>>>(mWih, mWih_p, 600, DD);
        n = 600 * KP;  prep_pad<<<(n + 255) / 256, 256>>>(mWhh, mWhh_p, 600, DD);
        n = 200 * KP;  prep_trans<<<(n + 255) / 256, 256>>>(W_atom, WT_atom, 1, FAA, DD);
        n = 200 * KP;  prep_trans<<<(n + 255) / 256, 256>>>(W_nei, WT_nei, 1, FC, DD);
        n = 3 * 200 * KP; prep_trans<<<(n + 255) / 256, 256>>>(W_attend, WT_att, 3, DD, DD);
        n = 200 * KP;  prep_trans<<<(n + 255) / 256, 256>>>(W_mol_att, WT_molatt, 1, DD, DD);
    }

    // 1) atom_feature = lrelu(atom_list @ W_atom + b_atom)
    pad_atom_kernel<<<(NATOM * KPAD + 255) / 256, 256>>>(atom_list, atompad);
    tgemm(atompad, KPAD, KPAD, WT_atom, b_atom, nullptr, atomfeat, NATOM, DD, 1);

    // 2) nei0 = lrelu(concat @ W_nei + b_nei)
    build_concat<<<(NROWN * KPAD + 255) / 256, 256>>>(atom_list, bond_list, adeg, bdeg, concat);
    tgemm(concat, KPAD, KPAD, WT_nei, b_nei, nullptr, nei0, NROWN, DD, 1);

    // 3) atom GRU rounds: ctx = elu(wsum @ W_attend + wtot*b_attend)
    for (int r = 0; r < RR; r++) {
        const float* curp = (r == 0) ? atomfeat : cur;
        ctx_kernel<<<NATOM, 256>>>(curp, (r == 0) ? nei0 : nullptr, adeg,
                                   W_align + (size_t)r * D2, b_align + r,
                                   wsum, wtot, (r == 0) ? 1 : 0);
        tgemm(wsum, DD, DD, WT_att + (size_t)r * 200 * KP, b_attend + r * DD, wtot,
              ctx, NATOM, DD, 2);
        tgemm(ctx, DD, DD, Wih_p + (size_t)r * D3 * KP, bih + r * D3, nullptr, gi, NATOM, D3, 0);
        tgemm(h,   DD, DD, Whh_p + (size_t)r * D3 * KP, bhh + r * D3, nullptr, gh, NATOM, D3, 0);
        gru_combine<<<(NATOM * DD + 255) / 256, 256>>>(gi, gh, h, h, cur, NATOM);
    }

    // 4) mol phase
    molprep_kernel<<<BDIM, 256>>>(cur, amask, W_mol_align, mol, actmol, s2);
    for (int t = 0; t < TTI; t++) {
        molctx_kernel<<<BDIM, 256>>>(actmol, cur, s2, amask, W_mol_align, b_mol_align,
                                     mwsum, mwtot);
        tgemm(mwsum, DD, DD, WT_molatt, b_mol_att, mwtot, mctx, BDIM, DD, 2);
        tgemm(mctx, DD, DD, mWih_p, mbih, nullptr, mgi, BDIM, D3, 0);
        tgemm(mol,  DD, DD, mWhh_p, mbhh, nullptr, mgh, BDIM, D3, 0);
        gru_combine<<<(BDIM * DD + 255) / 256, 256>>>(mgi, mgh, mol, mol, actmol, BDIM);
    }

    // 5) final projection
    final_kernel<<<BDIM, 256>>>(mol, W_metric, b_metric, W_out, b_out, (float*)d_out);
}

// round 8
// speedup vs baseline: 2.2725x; 1.3963x over previous
#include <cuda_runtime.h>
#include <cuda_bf16.h>
#include <math.h>
#include <stdint.h>

typedef unsigned long long u64;

#define BDIM 128
#define LDIM 128
#define NNEI 6
#define FAA 39
#define FBB 10
#define FC 49
#define DD 200
#define D2 400
#define D3 600
#define RR 3
#define TTI 2
#define MBOND 256
#define NEGV -9e8f
#define NATOM (BDIM*LDIM)    /* 16384 */
#define NROWN (NATOM*NNEI)   /* 98304 */
#define KPAD 64
#define KP 224               /* padded K for weight buffers */
#define KPW (KP/2)           /* packed pairs per row = 112 */

// ---------------- device scratch (static, no allocation) ----------------
__device__ float g_atomfeat[NATOM*DD];   // also serves as h (updated in place)
__device__ float g_atompad[NATOM*KPAD];
__device__ float g_cur[NATOM*DD];
__device__ float g_ctx[NATOM*DD];
__device__ float g_wsum[NATOM*DD];
__device__ float g_wtot[NATOM];
__device__ float g_concat[NROWN*KPAD];
__device__ float g_nei0[NROWN*DD];
__device__ float g_gi[NATOM*D3];
__device__ float g_gh[NATOM*D3];
__device__ float g_s2[NATOM];
__device__ float g_mol[BDIM*DD];
__device__ float g_actmol[BDIM*DD];
__device__ float g_mwsum[BDIM*DD];
__device__ float g_mwtot[BDIM];
__device__ float g_mctx[BDIM*DD];
__device__ float g_mgi[BDIM*D3];
__device__ float g_mgh[BDIM*D3];
// packed bf16-pair weights [N, KPW] (hi and lo planes)
__device__ uint32_t g_WT_atom_h[200*KPW],  g_WT_atom_l[200*KPW];
__device__ uint32_t g_WT_nei_h[200*KPW],   g_WT_nei_l[200*KPW];
__device__ uint32_t g_WT_att_h[3*200*KPW], g_WT_att_l[3*200*KPW];
__device__ uint32_t g_WT_molatt_h[200*KPW],g_WT_molatt_l[200*KPW];
__device__ uint32_t g_Wih_h[3*600*KPW],    g_Wih_l[3*600*KPW];
__device__ uint32_t g_Whh_h[3*600*KPW],    g_Whh_l[3*600*KPW];
__device__ uint32_t g_mWih_h[600*KPW],     g_mWih_l[600*KPW];
__device__ uint32_t g_mWhh_h[600*KPW],     g_mWhh_l[600*KPW];

// ---------------- helpers ----------------
__device__ __forceinline__ float warpsum(float v) {
    #pragma unroll
    for (int o = 16; o > 0; o >>= 1) v += __shfl_down_sync(0xffffffffu, v, o);
    return v;
}
__device__ __forceinline__ float lrelu(float x) { return x > 0.f ? x : 0.01f * x; }
__device__ __forceinline__ float eluf(float x)  { return x > 0.f ? x : expm1f(x); }
__device__ __forceinline__ float sigm(float x)  { return 1.f / (1.f + expf(-x)); }

// split x into bf16 hi + bf16 lo, return packed pair builders
__device__ __forceinline__ void split_bf16(float x, __nv_bfloat16& h, __nv_bfloat16& l) {
    h = __float2bfloat16_rn(x);
    l = __float2bfloat16_rn(x - __bfloat162float(h));
}
__device__ __forceinline__ uint32_t pack2(__nv_bfloat16 a, __nv_bfloat16 b) {
    __nv_bfloat162 p = __halves2bfloat162(a, b);   // .x = a (low), .y = b (high)
    return *reinterpret_cast<uint32_t*>(&p);
}

#define MMAB(c, a, b) \
    asm volatile("mma.sync.aligned.m16n8k16.row.col.f32.bf16.bf16.f32 " \
        "{%0,%1,%2,%3}, {%4,%5,%6,%7}, {%8,%9}, {%0,%1,%2,%3};" \
        : "+f"((c)[0]), "+f"((c)[1]), "+f"((c)[2]), "+f"((c)[3]) \
        : "r"((a)[0]), "r"((a)[1]), "r"((a)[2]), "r"((a)[3]), \
          "r"((b)[0]), "r"((b)[1]))

// =====================================================================
// Split-bf16 tensor GEMM: C[M,Ntot] = act(A[M,K](lda) @ WT^T + rs[m]*bias)
// WTh/WTl: [Ntot, KPW] packed bf16-pairs (hi/lo planes), zero-padded.
// acc = Ah*Bh + Ah*Bl + Al*Bh in fp32  (~17-bit mantissa operands)
// BM=128, BN=64, BK=16. 256 threads = 8 warps (4m x 2n), warp tile 32x32.
// =====================================================================
__global__ __launch_bounds__(256) void bfgemm_kernel(
    const float* __restrict__ A, int lda, int K,
    const uint32_t* __restrict__ WTh, const uint32_t* __restrict__ WTl,
    const float* __restrict__ bias,
    const float* __restrict__ rowscale,
    float* __restrict__ C, int M, int Ntot, int act)
{
    __shared__ uint32_t APh[8][132], APl[8][132];
    __shared__ uint32_t BPh[8][72],  BPl[8][72];

    const int tid = threadIdx.x;
    const int wid = tid >> 5;
    const int lane = tid & 31;
    const int gid = lane >> 2;      // 0..7
    const int tg = lane & 3;        // 0..3
    const int bm0 = blockIdx.x * 128;
    const int bn0 = blockIdx.y * 64;
    const int wm = (wid & 3) * 32;
    const int wn = (wid >> 2) * 32;

    float c[2][4][4];
    #pragma unroll
    for (int mt = 0; mt < 2; mt++)
        #pragma unroll
        for (int nt = 0; nt < 4; nt++)
            #pragma unroll
            for (int q = 0; q < 4; q++) c[mt][nt][q] = 0.f;

    const int nch = (K + 15) >> 4;
    for (int ch = 0; ch < nch; ch++) {
        const int k0 = ch << 4;
        // stage A tile: 128 rows x 16 k = 512 float4 (2/thread), split+pack
        #pragma unroll
        for (int it = 0; it < 2; it++) {
            int i = tid + it * 256;
            int r = i >> 2, c4 = (i & 3) << 2;     // k offsets c4..c4+3 (4 | K)
            int k = k0 + c4;
            float4 v = make_float4(0.f, 0.f, 0.f, 0.f);
            if (k < K) v = *reinterpret_cast<const float4*>(A + (size_t)(bm0 + r) * lda + k);
            __nv_bfloat16 h0, l0, h1, l1, h2, l2, h3, l3;
            split_bf16(v.x, h0, l0); split_bf16(v.y, h1, l1);
            split_bf16(v.z, h2, l2); split_bf16(v.w, h3, l3);
            int kp = c4 >> 1;
            APh[kp][r]     = pack2(h0, h1);
            APh[kp + 1][r] = pack2(h2, h3);
            APl[kp][r]     = pack2(l0, l1);
            APl[kp + 1][r] = pack2(l2, l3);
        }
        // stage B tile: 64 rows x 8 kpairs, 1 uint2 per thread per plane
        {
            int r = tid >> 2, kp2 = (tid & 3) << 1;
            int n = bn0 + r;
            uint2 vh = make_uint2(0u, 0u), vl = make_uint2(0u, 0u);
            if (n < Ntot) {
                size_t off = (size_t)n * KPW + (k0 >> 1) + kp2;
                vh = *reinterpret_cast<const uint2*>(WTh + off);
                vl = *reinterpret_cast<const uint2*>(WTl + off);
            }
            BPh[kp2][r] = vh.x; BPh[kp2 + 1][r] = vh.y;
            BPl[kp2][r] = vl.x; BPl[kp2 + 1][r] = vl.y;
        }
        __syncthreads();

        uint32_t ah[2][4], al[2][4];
        #pragma unroll
        for (int mt = 0; mt < 2; mt++) {
            int mr = wm + mt * 16;
            ah[mt][0] = APh[tg][mr + gid];
            ah[mt][1] = APh[tg][mr + gid + 8];
            ah[mt][2] = APh[tg + 4][mr + gid];
            ah[mt][3] = APh[tg + 4][mr + gid + 8];
            al[mt][0] = APl[tg][mr + gid];
            al[mt][1] = APl[tg][mr + gid + 8];
            al[mt][2] = APl[tg + 4][mr + gid];
            al[mt][3] = APl[tg + 4][mr + gid + 8];
        }
        uint32_t bh[4][2], bl[4][2];
        #pragma unroll
        for (int nt = 0; nt < 4; nt++) {
            int nc = wn + nt * 8 + gid;
            bh[nt][0] = BPh[tg][nc];
            bh[nt][1] = BPh[tg + 4][nc];
            bl[nt][0] = BPl[tg][nc];
            bl[nt][1] = BPl[tg + 4][nc];
        }
        #pragma unroll
        for (int mt = 0; mt < 2; mt++)
            #pragma unroll
            for (int nt = 0; nt < 4; nt++) {
                MMAB(c[mt][nt], ah[mt], bh[nt]);
                MMAB(c[mt][nt], ah[mt], bl[nt]);
                MMAB(c[mt][nt], al[mt], bh[nt]);
            }
        __syncthreads();
    }

    // epilogue
    #pragma unroll
    for (int mt = 0; mt < 2; mt++) {
        #pragma unroll
        for (int half = 0; half < 2; half++) {
            int m = bm0 + wm + mt * 16 + gid + half * 8;
            float rs = rowscale ? rowscale[m] : 1.f;
            float* crow = C + (size_t)m * Ntot;
            #pragma unroll
            for (int nt = 0; nt < 4; nt++) {
                int n = bn0 + wn + nt * 8 + 2 * tg;
                float v0 = c[mt][nt][half * 2 + 0];
                float v1 = c[mt][nt][half * 2 + 1];
                if (n < Ntot) {
                    float v = v0 + rs * (bias ? bias[n] : 0.f);
                    if (act == 1) v = lrelu(v);
                    else if (act == 2) v = eluf(v);
                    crow[n] = v;
                }
                if (n + 1 < Ntot) {
                    float v = v1 + rs * (bias ? bias[n + 1] : 0.f);
                    if (act == 1) v = lrelu(v);
                    else if (act == 2) v = eluf(v);
                    crow[n + 1] = v;
                }
            }
        }
    }
}

// ---------------- weight prep: [NT,K] row-major -> packed hi/lo [NT,KPW] ----------------
__global__ void prep_pad_bf(const float* __restrict__ in,
                            uint32_t* __restrict__ outh, uint32_t* __restrict__ outl,
                            int NT, int K)
{
    int i = blockIdx.x * 256 + threadIdx.x;
    if (i >= NT * KPW) return;
    int n = i / KPW, kp = i - n * KPW;
    int k = kp << 1;
    float x0 = (k < K) ? in[(size_t)n * K + k] : 0.f;
    float x1 = (k + 1 < K) ? in[(size_t)n * K + k + 1] : 0.f;
    __nv_bfloat16 h0, l0, h1, l1;
    split_bf16(x0, h0, l0); split_bf16(x1, h1, l1);
    outh[i] = pack2(h0, h1);
    outl[i] = pack2(l0, l1);
}

// ---------------- weight prep: [R,K,N] -> packed hi/lo [R,N,KPW] ----------------
__global__ void prep_trans_bf(const float* __restrict__ in,
                              uint32_t* __restrict__ outh, uint32_t* __restrict__ outl,
                              int R, int K, int N)
{
    int i = blockIdx.x * 256 + threadIdx.x;
    if (i >= R * N * KPW) return;
    int kp = i % KPW;
    int rn = i / KPW;
    int n = rn % N;
    int r = rn / N;
    int k = kp << 1;
    float x0 = (k < K) ? in[((size_t)r * K + k) * N + n] : 0.f;
    float x1 = (k + 1 < K) ? in[((size_t)r * K + k + 1) * N + n] : 0.f;
    __nv_bfloat16 h0, l0, h1, l1;
    split_bf16(x0, h0, l0); split_bf16(x1, h1, l1);
    outh[i] = pack2(h0, h1);
    outl[i] = pack2(l0, l1);
}

// ---------------- pad atom_list [NATOM,39] -> [NATOM,64] ----------------
__global__ void pad_atom_kernel(const float* __restrict__ atom_list, float* __restrict__ out)
{
    int i = blockIdx.x * blockDim.x + threadIdx.x;
    if (i >= NATOM * KPAD) return;
    int row = i >> 6;
    int f = i & 63;
    out[i] = (f < FAA) ? atom_list[row * FAA + f] : 0.f;
}

// ---------------- build concat(atom_nei, bond_nei) [NROWN, 64] padded ----------------
__global__ void build_concat(const float* __restrict__ atom_list,
                             const float* __restrict__ bond_list,
                             const int* __restrict__ adeg,
                             const int* __restrict__ bdeg,
                             float* __restrict__ out)
{
    int i = blockIdx.x * blockDim.x + threadIdx.x;
    if (i >= NROWN * KPAD) return;
    int row = i >> 6;
    int f = i & 63;
    int b = row / (LDIM * NNEI);
    float v = 0.f;
    if (f < FAA) {
        int a = adeg[row];
        v = atom_list[((size_t)b * LDIM + a) * FAA + f];
    } else if (f < FC) {
        int bd = bdeg[row];
        v = bond_list[((size_t)b * MBOND + bd) * FBB + (f - FAA)];
    }
    out[i] = v;
}

// ---------------- attention: softmax weights + weighted neighbor sum ----------------
__global__ void ctx_kernel(const float* __restrict__ cur,
                           const float* __restrict__ neiBuf,
                           const int* __restrict__ adeg,
                           const float* __restrict__ Wal,
                           const float* __restrict__ bal,
                           float* __restrict__ wsum,
                           float* __restrict__ wtot,
                           int firstRound)
{
    const int atom = blockIdx.x;
    const int b = atom / LDIM;
    const int tid = threadIdx.x;
    const int lane = tid & 31;

    __shared__ float curS[DD];
    __shared__ float neiS[NNEI][DD];
    __shared__ float red[NNEI + 1];
    __shared__ int idxS[NNEI];

    if (tid <= NNEI) red[tid] = 0.f;
    if (tid < NNEI) idxS[tid] = adeg[atom * NNEI + tid];
    for (int d = tid; d < DD; d += 256) curS[d] = cur[(size_t)atom * DD + d];
    __syncthreads();

    #pragma unroll
    for (int n = 0; n < NNEI; n++) {
        const float* src = firstRound ? (neiBuf + ((size_t)atom * NNEI + n) * DD)
                                      : (cur + ((size_t)(b * LDIM + idxS[n])) * DD);
        for (int d = tid; d < DD; d += 256) neiS[n][d] = src[d];
    }
    __syncthreads();

    float p[NNEI + 1];
    #pragma unroll
    for (int n = 0; n <= NNEI; n++) p[n] = 0.f;
    for (int d = tid; d < DD; d += 256) {
        float a1 = Wal[d];
        float a2 = Wal[DD + d];
        p[NNEI] += a1 * curS[d];
        #pragma unroll
        for (int n = 0; n < NNEI; n++) p[n] += a2 * neiS[n][d];
    }
    #pragma unroll
    for (int n = 0; n <= NNEI; n++) {
        float s = warpsum(p[n]);
        if (lane == 0) atomicAdd(&red[n], s);
    }
    __syncthreads();

    float dtop = red[NNEI];
    float bb = bal[0];
    float sc[NNEI];
    float msk[NNEI];
    float mx = -1e30f;
    #pragma unroll
    for (int n = 0; n < NNEI; n++) {
        float a = lrelu(dtop + red[n] + bb);
        bool pad = (idxS[n] == LDIM - 1);
        msk[n] = pad ? 0.f : 1.f;
        a += pad ? NEGV : 0.f;
        sc[n] = a;
        mx = fmaxf(mx, a);
    }
    float sum = 0.f;
    float w[NNEI];
    #pragma unroll
    for (int n = 0; n < NNEI; n++) { w[n] = expf(sc[n] - mx); sum += w[n]; }
    float inv = 1.f / sum;
    float wt = 0.f;
    #pragma unroll
    for (int n = 0; n < NNEI; n++) { w[n] = w[n] * inv * msk[n]; wt += w[n]; }

    for (int d = tid; d < DD; d += 256) {
        float s = 0.f;
        #pragma unroll
        for (int n = 0; n < NNEI; n++) s += w[n] * neiS[n][d];
        wsum[(size_t)atom * DD + d] = s;
    }
    if (tid == 0) wtot[atom] = wt;
}

// ---------------- GRU combine ----------------
__global__ void gru_combine(const float* __restrict__ gi, const float* __restrict__ gh,
                            const float* __restrict__ h,
                            float* __restrict__ hOut, float* __restrict__ actOut, int Mrows)
{
    int i = blockIdx.x * blockDim.x + threadIdx.x;
    if (i >= Mrows * DD) return;
    int m = i / DD;
    int d = i - m * DD;
    const float* gim = gi + (size_t)m * D3;
    const float* ghm = gh + (size_t)m * D3;
    float r = sigm(gim[d] + ghm[d]);
    float z = sigm(gim[DD + d] + ghm[DD + d]);
    float n = tanhf(gim[2 * DD + d] + r * ghm[2 * DD + d]);
    float hv = h[i];
    float hn = (1.f - z) * n + z * hv;
    hOut[i] = hn;
    actOut[i] = hn > 0.f ? hn : 0.f;
}

// ---------------- mol prep: masked sum + per-atom s2 dot ----------------
__global__ void molprep_kernel(const float* __restrict__ cur, const float* __restrict__ amask,
                               const float* __restrict__ Wma,
                               float* __restrict__ mol, float* __restrict__ actmol,
                               float* __restrict__ s2)
{
    int b = blockIdx.x;
    int tid = threadIdx.x;
    for (int d = tid; d < DD; d += 256) {
        float s = 0.f;
        for (int l = 0; l < LDIM; l++)
            s += cur[((size_t)b * LDIM + l) * DD + d] * amask[b * LDIM + l];
        mol[b * DD + d] = s;
        actmol[b * DD + d] = s > 0.f ? s : 0.f;
    }
    int w = tid >> 5;
    int lane = tid & 31;
    for (int l = w; l < LDIM; l += 8) {
        float p = 0.f;
        const float* row = cur + ((size_t)b * LDIM + l) * DD;
        for (int d = lane; d < DD; d += 32) p += row[d] * Wma[DD + d];
        p = warpsum(p);
        if (lane == 0) s2[b * LDIM + l] = p;
    }
}

// ---------------- mol attention: weights + weighted atom sum ----------------
__global__ void molctx_kernel(const float* __restrict__ actmol,
                              const float* __restrict__ cur,
                              const float* __restrict__ s2,
                              const float* __restrict__ amask,
                              const float* __restrict__ Wma,
                              const float* __restrict__ bma,
                              float* __restrict__ mwsum,
                              float* __restrict__ mwtot)
{
    int b = blockIdx.x;
    int tid = threadIdx.x;
    int lane = tid & 31;
    __shared__ float redv;
    __shared__ float sc[LDIM];
    __shared__ float wS[LDIM];
    if (tid == 0) redv = 0.f;
    __syncthreads();

    float p = 0.f;
    for (int d = tid; d < DD; d += 256) p += actmol[b * DD + d] * Wma[d];
    p = warpsum(p);
    if (lane == 0) atomicAdd(&redv, p);
    __syncthreads();

    if (tid < LDIM) {
        float a = lrelu(redv + s2[b * LDIM + tid] + bma[0]);
        if (amask[b * LDIM + tid] == 0.f) a += NEGV;
        sc[tid] = a;
    }
    __syncthreads();

    float mx = -1e30f;
    for (int l = 0; l < LDIM; l++) mx = fmaxf(mx, sc[l]);
    float sum = 0.f;
    for (int l = 0; l < LDIM; l++) sum += expf(sc[l] - mx);
    float inv = 1.f / sum;
    if (tid < LDIM) wS[tid] = expf(sc[tid] - mx) * inv * amask[b * LDIM + tid];
    __syncthreads();

    for (int d = tid; d < DD; d += 256) {
        float s = 0.f;
        for (int l = 0; l < LDIM; l++)
            s += wS[l] * cur[((size_t)b * LDIM + l) * DD + d];
        mwsum[b * DD + d] = s;
    }
    if (tid == 0) {
        float wt = 0.f;
        for (int l = 0; l < LDIM; l++) wt += wS[l];
        mwtot[b] = wt;
    }
}

// ---------------- final projection ----------------
__global__ void final_kernel(const float* __restrict__ mol,
                             const float* __restrict__ Wm, const float* __restrict__ bm,
                             const float* __restrict__ Wo, const float* __restrict__ bo,
                             float* __restrict__ out)
{
    int b = blockIdx.x;
    int tid = threadIdx.x;
    int lane = tid & 31;
    __shared__ float featS[D2];
    __shared__ float ws[8];
    for (int j = tid; j < D2; j += 256)
        featS[j] = (j < DD) ? mol[b * DD + j] : (mol[b * DD + j - DD] + (float)(RR - 2));
    __syncthreads();
    float p = 0.f;
    for (int d = tid; d < DD; d += 256) {
        float s = bm[d];
        for (int j = 0; j < D2; j++) s += featS[j] * Wm[j * DD + d];
        p += s * Wo[d];
    }
    p = warpsum(p);
    if (lane == 0) ws[tid >> 5] = p;
    __syncthreads();
    if (tid == 0) {
        float t = 0.f;
        for (int i = 0; i < 8; i++) t += ws[i];
        out[b] = t + bo[0];
    }
}

// ---------------- host-side tensor GEMM dispatch ----------------
static void tgemm(const float* A, int lda, int K,
                  const uint32_t* WTh, const uint32_t* WTl,
                  const float* bias, const float* rowscale, float* C,
                  int M, int Ntot, int act)
{
    dim3 g(M / 128, (Ntot + 63) / 64);
    bfgemm_kernel<<<g, 256>>>(A, lda, K, WTh, WTl, bias, rowscale, C, M, Ntot, act);
}

extern "C" void kernel_launch(void* const* d_in, const int* in_sizes, int n_in,
                              void* d_out, int out_size)
{
    const float* atom_list   = (const float*)d_in[0];
    const float* bond_list   = (const float*)d_in[1];
    const int*   adeg        = (const int*)d_in[2];
    const int*   bdeg        = (const int*)d_in[3];
    const float* amask       = (const float*)d_in[4];
    const float* W_atom      = (const float*)d_in[5];
    const float* b_atom      = (const float*)d_in[6];
    const float* W_nei       = (const float*)d_in[7];
    const float* b_nei       = (const float*)d_in[8];
    const float* W_align     = (const float*)d_in[9];
    const float* b_align     = (const float*)d_in[10];
    const float* W_attend    = (const float*)d_in[11];
    const float* b_attend    = (const float*)d_in[12];
    const float* Wih         = (const float*)d_in[13];
    const float* Whh         = (const float*)d_in[14];
    const float* bih         = (const float*)d_in[15];
    const float* bhh         = (const float*)d_in[16];
    const float* W_mol_align = (const float*)d_in[17];
    const float* b_mol_align = (const float*)d_in[18];
    const float* W_mol_att   = (const float*)d_in[19];
    const float* b_mol_att   = (const float*)d_in[20];
    const float* mWih        = (const float*)d_in[21];
    const float* mWhh        = (const float*)d_in[22];
    const float* mbih        = (const float*)d_in[23];
    const float* mbhh        = (const float*)d_in[24];
    const float* W_metric    = (const float*)d_in[25];
    const float* b_metric    = (const float*)d_in[26];
    const float* W_out       = (const float*)d_in[27];
    const float* b_out       = (const float*)d_in[28];

    float *atomfeat, *atompad, *cur, *ctx, *wsum, *wtot, *concat, *nei0, *gi, *gh;
    float *s2, *mol, *actmol, *mwsum, *mwtot, *mctx, *mgi, *mgh;
    uint32_t *WT_atom_h, *WT_atom_l, *WT_nei_h, *WT_nei_l, *WT_att_h, *WT_att_l;
    uint32_t *WT_molatt_h, *WT_molatt_l, *Wih_h, *Wih_l, *Whh_h, *Whh_l;
    uint32_t *mWih_h, *mWih_l, *mWhh_h, *mWhh_l;
    cudaGetSymbolAddress((void**)&atomfeat, g_atomfeat);
    cudaGetSymbolAddress((void**)&atompad, g_atompad);
    cudaGetSymbolAddress((void**)&cur, g_cur);
    cudaGetSymbolAddress((void**)&ctx, g_ctx);
    cudaGetSymbolAddress((void**)&wsum, g_wsum);
    cudaGetSymbolAddress((void**)&wtot, g_wtot);
    cudaGetSymbolAddress((void**)&concat, g_concat);
    cudaGetSymbolAddress((void**)&nei0, g_nei0);
    cudaGetSymbolAddress((void**)&gi, g_gi);
    cudaGetSymbolAddress((void**)&gh, g_gh);
    cudaGetSymbolAddress((void**)&s2, g_s2);
    cudaGetSymbolAddress((void**)&mol, g_mol);
    cudaGetSymbolAddress((void**)&actmol, g_actmol);
    cudaGetSymbolAddress((void**)&mwsum, g_mwsum);
    cudaGetSymbolAddress((void**)&mwtot, g_mwtot);
    cudaGetSymbolAddress((void**)&mctx, g_mctx);
    cudaGetSymbolAddress((void**)&mgi, g_mgi);
    cudaGetSymbolAddress((void**)&mgh, g_mgh);
    cudaGetSymbolAddress((void**)&WT_atom_h, g_WT_atom_h);
    cudaGetSymbolAddress((void**)&WT_atom_l, g_WT_atom_l);
    cudaGetSymbolAddress((void**)&WT_nei_h, g_WT_nei_h);
    cudaGetSymbolAddress((void**)&WT_nei_l, g_WT_nei_l);
    cudaGetSymbolAddress((void**)&WT_att_h, g_WT_att_h);
    cudaGetSymbolAddress((void**)&WT_att_l, g_WT_att_l);
    cudaGetSymbolAddress((void**)&WT_molatt_h, g_WT_molatt_h);
    cudaGetSymbolAddress((void**)&WT_molatt_l, g_WT_molatt_l);
    cudaGetSymbolAddress((void**)&Wih_h, g_Wih_h);
    cudaGetSymbolAddress((void**)&Wih_l, g_Wih_l);
    cudaGetSymbolAddress((void**)&Whh_h, g_Whh_h);
    cudaGetSymbolAddress((void**)&Whh_l, g_Whh_l);
    cudaGetSymbolAddress((void**)&mWih_h, g_mWih_h);
    cudaGetSymbolAddress((void**)&mWih_l, g_mWih_l);
    cudaGetSymbolAddress((void**)&mWhh_h, g_mWhh_h);
    cudaGetSymbolAddress((void**)&mWhh_l, g_mWhh_l);

    float* h = atomfeat;   // h aliases atomfeat; updated in place by gru_combine

    // 0) weight prep (split to bf16 hi/lo, pack pairs, K-major [N, KPW])
    {
        int n;
        n = 1800 * KPW; prep_pad_bf<<<(n + 255) / 256, 256>>>(Wih, Wih_h, Wih_l, 1800, DD);
        n = 1800 * KPW; prep_pad_bf<<<(n + 255) / 256, 256>>>(Whh, Whh_h, Whh_l, 1800, DD);
        n = 600 * KPW;  prep_pad_bf<<<(n + 255) / 256, 256>>>(mWih, mWih_h, mWih_l, 600, DD);
        n = 600 * KPW;  prep_pad_bf<<<(n + 255) / 256, 256>>>(mWhh, mWhh_h, mWhh_l, 600, DD);
        n = 200 * KPW;  prep_trans_bf<<<(n + 255) / 256, 256>>>(W_atom, WT_atom_h, WT_atom_l, 1, FAA, DD);
        n = 200 * KPW;  prep_trans_bf<<<(n + 255) / 256, 256>>>(W_nei, WT_nei_h, WT_nei_l, 1, FC, DD);
        n = 3 * 200 * KPW; prep_trans_bf<<<(n + 255) / 256, 256>>>(W_attend, WT_att_h, WT_att_l, 3, DD, DD);
        n = 200 * KPW;  prep_trans_bf<<<(n + 255) / 256, 256>>>(W_mol_att, WT_molatt_h, WT_molatt_l, 1, DD, DD);
    }

    // 1) atom_feature = lrelu(atom_list @ W_atom + b_atom)
    pad_atom_kernel<<<(NATOM * KPAD + 255) / 256, 256>>>(atom_list, atompad);
    tgemm(atompad, KPAD, KPAD, WT_atom_h, WT_atom_l, b_atom, nullptr, atomfeat, NATOM, DD, 1);

    // 2) nei0 = lrelu(concat @ W_nei + b_nei)
    build_concat<<<(NROWN * KPAD + 255) / 256, 256>>>(atom_list, bond_list, adeg, bdeg, concat);
    tgemm(concat, KPAD, KPAD, WT_nei_h, WT_nei_l, b_nei, nullptr, nei0, NROWN, DD, 1);

    // 3) atom GRU rounds: ctx = elu(wsum @ W_attend + wtot*b_attend)
    for (int r = 0; r < RR; r++) {
        const float* curp = (r == 0) ? atomfeat : cur;
        ctx_kernel<<<NATOM, 256>>>(curp, (r == 0) ? nei0 : nullptr, adeg,
                                   W_align + (size_t)r * D2, b_align + r,
                                   wsum, wtot, (r == 0) ? 1 : 0);
        tgemm(wsum, DD, DD, WT_att_h + (size_t)r * 200 * KPW, WT_att_l + (size_t)r * 200 * KPW,
              b_attend + r * DD, wtot, ctx, NATOM, DD, 2);
        tgemm(ctx, DD, DD, Wih_h + (size_t)r * D3 * KPW, Wih_l + (size_t)r * D3 * KPW,
              bih + r * D3, nullptr, gi, NATOM, D3, 0);
        tgemm(h,   DD, DD, Whh_h + (size_t)r * D3 * KPW, Whh_l + (size_t)r * D3 * KPW,
              bhh + r * D3, nullptr, gh, NATOM, D3, 0);
        gru_combine<<<(NATOM * DD + 255) / 256, 256>>>(gi, gh, h, h, cur, NATOM);
    }

    // 4) mol phase
    molprep_kernel<<<BDIM, 256>>>(cur, amask, W_mol_align, mol, actmol, s2);
    for (int t = 0; t < TTI; t++) {
        molctx_kernel<<<BDIM, 256>>>(actmol, cur, s2, amask, W_mol_align, b_mol_align,
                                     mwsum, mwtot);
        tgemm(mwsum, DD, DD, WT_molatt_h, WT_molatt_l, b_mol_att, mwtot, mctx, BDIM, DD, 2);
        tgemm(mctx, DD, DD, mWih_h, mWih_l, mbih, nullptr, mgi, BDIM, D3, 0);
        tgemm(mol,  DD, DD, mWhh_h, mWhh_l, mbhh, nullptr, mgh, BDIM, D3, 0);
        gru_combine<<<(BDIM * DD + 255) / 256, 256>>>(mgi, mgh, mol, mol, actmol, BDIM);
    }

    // 5) final projection
    final_kernel<<<BDIM, 256>>>(mol, W_metric, b_metric, W_out, b_out, (float*)d_out);
}